// round 8
// baseline (speedup 1.0000x reference)
#include <cuda_runtime.h>
#include <math.h>
#include <stdint.h>

// Problem dims (fixed)
#define BB   2
#define LL   2048
#define DDIM 1024
#define HH   16
#define DHD  64
#define DFFN 4096
#define MROWS (BB*LL)   // 4096 token rows

// ---------------------------------------------------------------------------
// Scratch (device globals; no runtime allocation allowed)
// ---------------------------------------------------------------------------
__device__ float g_h   [(size_t)MROWS * DDIM];
__device__ float g_qkv [(size_t)MROWS * DDIM * 3];   // q | k | v
__device__ float g_ctx [(size_t)MROWS * DDIM];
__device__ float g_x1  [(size_t)MROWS * DDIM];
__device__ float g_f   [(size_t)MROWS * DFFN];
// tf32-rounded weights: wqkv = [3072][1024] NT; wo NT; w1T/w2T transposed to NT
__device__ float g_wqkv[(size_t)3 * DDIM * DDIM];
__device__ float g_wo  [(size_t)DDIM * DDIM];
__device__ float g_w1T [(size_t)DFFN * DDIM];        // [N=4096][K=1024]
__device__ float g_w2T [(size_t)DDIM * DFFN];        // [N=1024][K=4096]

// ---------------------------------------------------------------------------
// PTX helpers
// ---------------------------------------------------------------------------
__device__ __forceinline__ uint32_t smem_u32(const void* p) {
    return (uint32_t)__cvta_generic_to_shared(p);
}
__device__ __forceinline__ void cp_async16(uint32_t dst, const void* src) {
    asm volatile("cp.async.cg.shared.global [%0], [%1], 16;" :: "r"(dst), "l"(src));
}
__device__ __forceinline__ void cp_commit() {
    asm volatile("cp.async.commit_group;");
}
template<int N>
__device__ __forceinline__ void cp_wait() {
    asm volatile("cp.async.wait_group %0;" :: "n"(N));
}
__device__ __forceinline__ float rna(float f) {
    uint32_t r;
    asm("cvt.rna.tf32.f32 %0, %1;" : "=r"(r) : "f"(f));
    return __uint_as_float(r);
}
__device__ __forceinline__ void mma_tf32(float* c, const uint32_t* a, const uint32_t* b) {
    asm volatile(
        "mma.sync.aligned.m16n8k8.row.col.f32.tf32.tf32.f32 "
        "{%0,%1,%2,%3},{%4,%5,%6,%7},{%8,%9},{%0,%1,%2,%3};"
        : "+f"(c[0]), "+f"(c[1]), "+f"(c[2]), "+f"(c[3])
        : "r"(a[0]), "r"(a[1]), "r"(a[2]), "r"(a[3]), "r"(b[0]), "r"(b[1]));
}
__device__ __forceinline__ void ldsm_x4(uint32_t* r, uint32_t addr) {
    asm volatile("ldmatrix.sync.aligned.m8n8.x4.shared.b16 {%0,%1,%2,%3}, [%4];"
        : "=r"(r[0]), "=r"(r[1]), "=r"(r[2]), "=r"(r[3]) : "r"(addr));
}
__device__ __forceinline__ void ldsm_x2(uint32_t* r, uint32_t addr) {
    asm volatile("ldmatrix.sync.aligned.m8n8.x2.shared.b16 {%0,%1}, [%2];"
        : "=r"(r[0]), "=r"(r[1]) : "r"(addr));
}

// ---------------------------------------------------------------------------
// Round fp32 -> tf32 (rna) elementwise, float4 per thread
// ---------------------------------------------------------------------------
__global__ void __launch_bounds__(256) round_kernel(const float* __restrict__ in,
                                                    float* __restrict__ out, int n4) {
    int i = blockIdx.x * 256 + threadIdx.x;
    if (i < n4) {
        float4 v = ((const float4*)in)[i];
        v.x = rna(v.x); v.y = rna(v.y); v.z = rna(v.z); v.w = rna(v.w);
        ((float4*)out)[i] = v;
    }
}

// ---------------------------------------------------------------------------
// Transpose + round: in[R][C] -> out[C][R] (tf32-rounded). block (32,8), grid (C/32, R/32)
// ---------------------------------------------------------------------------
__global__ void __launch_bounds__(256) roundT_kernel(const float* __restrict__ in,
                                                     float* __restrict__ out,
                                                     int R, int C) {
    __shared__ float t[32][33];
    int bx = blockIdx.x * 32, by = blockIdx.y * 32;
    int x = threadIdx.x, y = threadIdx.y;
    #pragma unroll
    for (int i = 0; i < 32; i += 8)
        t[y + i][x] = in[(size_t)(by + y + i) * C + bx + x];
    __syncthreads();
    #pragma unroll
    for (int i = 0; i < 32; i += 8)
        out[(size_t)(bx + y + i) * R + by + x] = rna(t[x][y + i]);
}

// ---------------------------------------------------------------------------
// LayerNorm; rounds output to tf32 when it feeds a GEMM A operand
// ---------------------------------------------------------------------------
template<bool RND>
__global__ void __launch_bounds__(256) ln_kernel(const float* __restrict__ x,
                                                 const float* __restrict__ g,
                                                 const float* __restrict__ b,
                                                 float* __restrict__ out) {
    int row = blockIdx.x;
    int t = threadIdx.x;
    const float4* xr = (const float4*)(x + (size_t)row * DDIM);
    float4 v = xr[t];
    __shared__ float sred[8];

    float s = v.x + v.y + v.z + v.w;
    #pragma unroll
    for (int o = 16; o > 0; o >>= 1) s += __shfl_xor_sync(0xffffffffu, s, o);
    if ((t & 31) == 0) sred[t >> 5] = s;
    __syncthreads();
    float tot = 0.f;
    #pragma unroll
    for (int w = 0; w < 8; w++) tot += sred[w];
    float mu = tot * (1.0f / DDIM);

    float dx = v.x - mu, dy = v.y - mu, dz = v.z - mu, dw = v.w - mu;
    float s2 = dx*dx + dy*dy + dz*dz + dw*dw;
    #pragma unroll
    for (int o = 16; o > 0; o >>= 1) s2 += __shfl_xor_sync(0xffffffffu, s2, o);
    __syncthreads();
    if ((t & 31) == 0) sred[t >> 5] = s2;
    __syncthreads();
    float tv = 0.f;
    #pragma unroll
    for (int w = 0; w < 8; w++) tv += sred[w];
    float rstd = rsqrtf(tv * (1.0f / DDIM) + 1e-5f);

    float4 gg = ((const float4*)g)[t];
    float4 bb = ((const float4*)b)[t];
    float4 o4;
    o4.x = dx * rstd * gg.x + bb.x;
    o4.y = dy * rstd * gg.y + bb.y;
    o4.z = dz * rstd * gg.z + bb.z;
    o4.w = dw * rstd * gg.w + bb.w;
    if (RND) { o4.x = rna(o4.x); o4.y = rna(o4.y); o4.z = rna(o4.z); o4.w = rna(o4.w); }
    ((float4*)(out + (size_t)row * DDIM))[t] = o4;
}

// ---------------------------------------------------------------------------
// tf32 tensor-core GEMM (NT only): C[M,N] = A[M,K] @ B[N,K]^T
// Inputs pre-rounded tf32 -> raw-bit operands exact.
// CTA 128x128x16, 8 warps (2x4), warp 64x32, mma.m16n8k8.
// 3-stage cp.async ring, one __syncthreads per k-tile; ldmatrix fragments.
// SPLIT: C is 3 concatenated [MROWS][1024] buffers, column block selects one.
// ---------------------------------------------------------------------------
#define BMT 128
#define BNT 128
#define BKT 16
#define NSTG 3
#define STG_F 2560
#define GEMM_SMEM (NSTG * STG_F * 2 * 4)

template<bool GELU, bool BIAS, bool RES, bool RND, bool SPLIT>
__global__ void __launch_bounds__(256) gemm_tc(
    const float* __restrict__ A, const float* __restrict__ Bm,
    const float* __restrict__ bias, const float* __restrict__ res,
    float* __restrict__ C, int M, int N, int K)
{
    extern __shared__ float sm[];
    float* As = sm;                  // [NSTG][2560]  ([row][k] stride 20)
    float* Bs = sm + NSTG * STG_F;   // [NSTG][2560]  ([n][k] stride 20)

    int tid  = threadIdx.x;
    int lane = tid & 31;
    int wid  = tid >> 5;
    int wm   = wid >> 2;
    int wn   = wid & 3;
    int m0 = blockIdx.y * BMT;
    int n0 = blockIdx.x * BNT;

    float acc[4][4][4];
    #pragma unroll
    for (int i = 0; i < 4; i++)
        #pragma unroll
        for (int j = 0; j < 4; j++)
            #pragma unroll
            for (int r = 0; r < 4; r++) acc[i][j][r] = 0.f;

    auto issue = [&](int st, int k0) {
        float* as = As + st * STG_F;
        float* bs = Bs + st * STG_F;
        #pragma unroll
        for (int i = 0; i < 2; i++) {
            int idx = tid + i * 256;
            int row = idx >> 2, c = idx & 3;
            cp_async16(smem_u32(as + row * 20 + c * 4),
                       A + (size_t)(m0 + row) * K + k0 + c * 4);
        }
        #pragma unroll
        for (int i = 0; i < 2; i++) {
            int idx = tid + i * 256;
            int row = idx >> 2, c = idx & 3;
            cp_async16(smem_u32(bs + row * 20 + c * 4),
                       Bm + (size_t)(n0 + row) * K + k0 + c * 4);
        }
        cp_commit();
    };

    int nk = K / BKT;
    issue(0, 0);
    issue(1, BKT);

    for (int kt = 0; kt < nk; kt++) {
        if (kt + 1 < nk) cp_wait<1>(); else cp_wait<0>();
        __syncthreads();

        if (kt + 2 < nk) issue((kt + 2) % NSTG, (kt + 2) * BKT);

        const float* as = As + (kt % NSTG) * STG_F;
        const float* bs = Bs + (kt % NSTG) * STG_F;
        #pragma unroll
        for (int ks = 0; ks < 2; ks++) {
            uint32_t af[4][4], bf[4][2];
            {
                int rowbase = wm * 64 + (lane & 15);
                int koff = ks * 8 + ((lane >> 4) << 2);
                #pragma unroll
                for (int mt = 0; mt < 4; mt++)
                    ldsm_x4(af[mt], smem_u32(as + (rowbase + mt * 16) * 20 + koff));
            }
            {
                int nb = wn * 32 + (lane & 7);
                int koff = ks * 8 + ((lane & 8) ? 4 : 0);
                #pragma unroll
                for (int nt = 0; nt < 4; nt++)
                    ldsm_x2(bf[nt], smem_u32(bs + (nb + nt * 8) * 20 + koff));
            }
            #pragma unroll
            for (int mt = 0; mt < 4; mt++)
                #pragma unroll
                for (int nt = 0; nt < 4; nt++)
                    mma_tf32(acc[mt][nt], af[mt], bf[nt]);
        }
    }

    // ---- epilogue ----
    float* Cb = C;
    int ldc = N, ncol0 = n0;
    if (SPLIT) {
        Cb = C + (size_t)(n0 >> 10) * ((size_t)MROWS * DDIM);
        ldc = DDIM;
        ncol0 = n0 & 1023;
    }
    #pragma unroll
    for (int mt = 0; mt < 4; mt++) {
        #pragma unroll
        for (int nt = 0; nt < 4; nt++) {
            int row = m0 + wm * 64 + mt * 16 + (lane >> 2);
            int nc  = wn * 32 + nt * 8 + (lane & 3) * 2;
            int col = ncol0 + nc;
            #pragma unroll
            for (int half = 0; half < 2; half++) {
                int r = row + half * 8;
                float v0 = acc[mt][nt][half * 2 + 0];
                float v1 = acc[mt][nt][half * 2 + 1];
                if (BIAS) { v0 += bias[n0 + nc]; v1 += bias[n0 + nc + 1]; }
                if (GELU) {
                    v0 = 0.5f * v0 * (1.0f + erff(v0 * 0.70710678118654752f));
                    v1 = 0.5f * v1 * (1.0f + erff(v1 * 0.70710678118654752f));
                }
                if (RES) {
                    const float2 rr = *(const float2*)(res + (size_t)r * ldc + col);
                    v0 += rr.x; v1 += rr.y;
                }
                if (RND) { v0 = rna(v0); v1 = rna(v1); }
                float2 o2; o2.x = v0; o2.y = v1;
                *(float2*)(Cb + (size_t)r * ldc + col) = o2;
            }
        }
    }
}

// ---------------------------------------------------------------------------
// Causal flash attention with tf32 tensor cores (validated in R7).
// ---------------------------------------------------------------------------
__global__ void __launch_bounds__(256) attn_kernel(
    const float* __restrict__ Q, const float* __restrict__ K,
    const float* __restrict__ V, float* __restrict__ O) {
    __shared__ float Qs[64][68];    // [r][d]
    __shared__ float Ks[32][68];    // [c][d]
    __shared__ float Vs[64][44];    // [d][c]
    __shared__ float Ps[64][36];    // [r][c]
    __shared__ float sm_m[64], sm_l[64], sm_fc[64];

    int tid  = threadIdx.x;
    int lane = tid & 31;
    int wid  = tid >> 5;
    int mi   = wid & 3;
    int whalf = wid >> 2;
    int qt = blockIdx.x;
    int bh = blockIdx.y;
    size_t base = (size_t)(bh / HH) * LL * DDIM + (size_t)(bh % HH) * DHD;
    int q0 = qt * 64;

    #pragma unroll
    for (int i = 0; i < 4; i++) {
        int e = tid + i * 256;
        int r = e >> 4, c4 = (e & 15) * 4;
        *(float4*)&Qs[r][c4] = *(const float4*)(Q + base + (size_t)(q0 + r) * DDIM + c4);
    }
    if (tid < 64) { sm_m[tid] = -3.0e38f; sm_l[tid] = 0.f; }

    float o[4][4];
    #pragma unroll
    for (int nt = 0; nt < 4; nt++)
        #pragma unroll
        for (int r = 0; r < 4; r++) o[nt][r] = 0.f;

    int r0 = mi * 16 + (lane >> 2);
    int r1 = r0 + 8;

    int nkt = (q0 + 64) / 32;
    for (int kt = 0; kt < nkt; kt++) {
        int k0 = kt * 32;
        __syncthreads();
        #pragma unroll
        for (int i = 0; i < 2; i++) {
            int e = tid + i * 256;
            int c = e >> 4, d4 = (e & 15) * 4;
            *(float4*)&Ks[c][d4] = *(const float4*)(K + base + (size_t)(k0 + c) * DDIM + d4);
        }
        #pragma unroll
        for (int i = 0; i < 8; i++) {
            int e = tid + i * 256;
            int c = e >> 6, d = e & 63;
            Vs[d][c] = V[base + (size_t)(k0 + c) * DDIM + d];
        }
        __syncthreads();

        // S = Q K^T (64x32), warp computes 16x16
        float cs[2][4];
        #pragma unroll
        for (int nt = 0; nt < 2; nt++)
            #pragma unroll
            for (int r = 0; r < 4; r++) cs[nt][r] = 0.f;
        #pragma unroll
        for (int ks = 0; ks < 8; ks++) {
            uint32_t aq[4], bk[2][2];
            int rowQ = mi * 16 + (lane & 15);
            int koff = ks * 8 + ((lane >> 4) << 2);
            ldsm_x4(aq, smem_u32(&Qs[rowQ][0] + koff));
            int nb = whalf * 16 + (lane & 7);
            int koffb = ks * 8 + ((lane & 8) ? 4 : 0);
            ldsm_x2(bk[0], smem_u32(&Ks[nb][0] + koffb));
            ldsm_x2(bk[1], smem_u32(&Ks[nb + 8][0] + koffb));
            mma_tf32(cs[0], aq, bk[0]);
            mma_tf32(cs[1], aq, bk[1]);
        }
        {
            int cb = whalf * 16 + (lane & 3) * 2;
            #pragma unroll
            for (int nt = 0; nt < 2; nt++) {
                int c0 = cb + nt * 8;
                float s00 = cs[nt][0] * 0.125f, s01 = cs[nt][1] * 0.125f;
                float s10 = cs[nt][2] * 0.125f, s11 = cs[nt][3] * 0.125f;
                if (k0 + c0     > q0 + r0) s00 = -3.0e38f;
                if (k0 + c0 + 1 > q0 + r0) s01 = -3.0e38f;
                if (k0 + c0     > q0 + r1) s10 = -3.0e38f;
                if (k0 + c0 + 1 > q0 + r1) s11 = -3.0e38f;
                float2 t0; t0.x = s00; t0.y = s01;
                float2 t1; t1.x = s10; t1.y = s11;
                *(float2*)&Ps[r0][c0] = t0;
                *(float2*)&Ps[r1][c0] = t1;
            }
        }
        __syncthreads();

        // online softmax: 4 threads per row
        {
            int row = tid >> 2;
            int qd  = tid & 3;
            float sv[8];
            #pragma unroll
            for (int j = 0; j < 8; j++) sv[j] = Ps[row][qd * 8 + j];
            float tmax = sv[0];
            #pragma unroll
            for (int j = 1; j < 8; j++) tmax = fmaxf(tmax, sv[j]);
            tmax = fmaxf(tmax, __shfl_xor_sync(0xffffffffu, tmax, 1));
            tmax = fmaxf(tmax, __shfl_xor_sync(0xffffffffu, tmax, 2));
            float mold = sm_m[row];
            float newm = fmaxf(mold, tmax);
            float fcr  = __expf(mold - newm);
            float tsum = 0.f;
            #pragma unroll
            for (int j = 0; j < 8; j++) {
                float p = __expf(sv[j] - newm);
                tsum += p;
                sv[j] = rna(p);
            }
            #pragma unroll
            for (int j = 0; j < 8; j++) Ps[row][qd * 8 + j] = sv[j];
            tsum += __shfl_xor_sync(0xffffffffu, tsum, 1);
            tsum += __shfl_xor_sync(0xffffffffu, tsum, 2);
            if (qd == 0) {
                sm_m[row]  = newm;
                sm_l[row]  = sm_l[row] * fcr + tsum;
                sm_fc[row] = fcr;
            }
        }
        __syncthreads();

        // O = O*fc + P V
        {
            float f0 = sm_fc[r0], f1 = sm_fc[r1];
            #pragma unroll
            for (int nt = 0; nt < 4; nt++) {
                o[nt][0] *= f0; o[nt][1] *= f0;
                o[nt][2] *= f1; o[nt][3] *= f1;
            }
            #pragma unroll
            for (int ks = 0; ks < 4; ks++) {
                uint32_t ap[4], bv[4][2];
                int rowP = mi * 16 + (lane & 15);
                int koff = ks * 8 + ((lane >> 4) << 2);
                ldsm_x4(ap, smem_u32(&Ps[rowP][0] + koff));
                int nb = whalf * 32 + (lane & 7);
                int koffb = ks * 8 + ((lane & 8) ? 4 : 0);
                #pragma unroll
                for (int nt = 0; nt < 4; nt++)
                    ldsm_x2(bv[nt], smem_u32(&Vs[nb + nt * 8][0] + koffb));
                #pragma unroll
                for (int nt = 0; nt < 4; nt++)
                    mma_tf32(o[nt], ap, bv[nt]);
            }
        }
    }

    __syncthreads();
    {
        float inv0 = 1.0f / sm_l[r0];
        float inv1 = 1.0f / sm_l[r1];
        #pragma unroll
        for (int nt = 0; nt < 4; nt++) {
            int col = whalf * 32 + nt * 8 + (lane & 3) * 2;
            float2 t0, t1;
            t0.x = rna(o[nt][0] * inv0); t0.y = rna(o[nt][1] * inv0);
            t1.x = rna(o[nt][2] * inv1); t1.y = rna(o[nt][3] * inv1);
            *(float2*)(O + base + (size_t)(q0 + r0) * DDIM + col) = t0;
            *(float2*)(O + base + (size_t)(q0 + r1) * DDIM + col) = t1;
        }
    }
}

// ---------------------------------------------------------------------------
// Launch sequence  (ordered so ncu -s 5 -c 1 profiles attn_kernel)
// ---------------------------------------------------------------------------
extern "C" void kernel_launch(void* const* d_in, const int* in_sizes, int n_in,
                              void* d_out, int out_size) {
    const float* x     = (const float*)d_in[0];
    const float* ln1_g = (const float*)d_in[2];
    const float* ln1_b = (const float*)d_in[3];
    const float* W_q   = (const float*)d_in[4];
    const float* W_k   = (const float*)d_in[5];
    const float* W_v   = (const float*)d_in[6];
    const float* W_o   = (const float*)d_in[7];
    const float* ln2_g = (const float*)d_in[8];
    const float* ln2_b = (const float*)d_in[9];
    const float* fc1_W = (const float*)d_in[10];
    const float* fc1_b = (const float*)d_in[11];
    const float* fc2_W = (const float*)d_in[12];
    const float* fc2_b = (const float*)d_in[13];
    float* out = (float*)d_out;

    float *h, *qkv, *ctx, *x1, *f, *wqkv, *wo, *w1T, *w2T;
    cudaGetSymbolAddress((void**)&h,    g_h);
    cudaGetSymbolAddress((void**)&qkv,  g_qkv);
    cudaGetSymbolAddress((void**)&ctx,  g_ctx);
    cudaGetSymbolAddress((void**)&x1,   g_x1);
    cudaGetSymbolAddress((void**)&f,    g_f);
    cudaGetSymbolAddress((void**)&wqkv, g_wqkv);
    cudaGetSymbolAddress((void**)&wo,   g_wo);
    cudaGetSymbolAddress((void**)&w1T,  g_w1T);
    cudaGetSymbolAddress((void**)&w2T,  g_w2T);

    float* q = qkv;
    float* k = qkv + (size_t)MROWS * DDIM;
    float* v = qkv + (size_t)2 * MROWS * DDIM;

    cudaFuncSetAttribute(gemm_tc<false, false, false, true , true >, cudaFuncAttributeMaxDynamicSharedMemorySize, GEMM_SMEM);
    cudaFuncSetAttribute(gemm_tc<false, false, true , false, false>, cudaFuncAttributeMaxDynamicSharedMemorySize, GEMM_SMEM);
    cudaFuncSetAttribute(gemm_tc<true , true , false, true , false>, cudaFuncAttributeMaxDynamicSharedMemorySize, GEMM_SMEM);
    cudaFuncSetAttribute(gemm_tc<false, true , true , false, false>, cudaFuncAttributeMaxDynamicSharedMemorySize, GEMM_SMEM);

    int nDD = DDIM * DDIM / 4;

    // 1-3) round QKV weights into concatenated buffer
    round_kernel<<<(nDD + 255) / 256, 256>>>(W_q, wqkv,            nDD);
    round_kernel<<<(nDD + 255) / 256, 256>>>(W_k, wqkv + nDD * 4,  nDD);
    round_kernel<<<(nDD + 255) / 256, 256>>>(W_v, wqkv + nDD * 8,  nDD);
    // 4) h = round(LN1(x))
    ln_kernel<true><<<MROWS, 256>>>(x, ln1_g, ln1_b, h);
    // 5) fused qkv = round(h @ Wqkv^T), split epilogue
    gemm_tc<false, false, false, true , true ><<<dim3(3 * DDIM / BNT, MROWS / BMT), 256, GEMM_SMEM>>>(
        h, wqkv, nullptr, nullptr, qkv, MROWS, 3 * DDIM, DDIM);
    // 6) ctx = round(attention(q,k,v))          <-- ncu -s 5 profiles this
    attn_kernel<<<dim3(LL / 64, BB * HH), 256>>>(q, k, v, ctx);
    // 7-9) round W_o; transpose+round fc1_W, fc2_W into NT layout
    round_kernel<<<(nDD + 255) / 256, 256>>>(W_o, wo, nDD);
    roundT_kernel<<<dim3(DFFN / 32, DDIM / 32), dim3(32, 8)>>>(fc1_W, w1T, DDIM, DFFN);
    roundT_kernel<<<dim3(DDIM / 32, DFFN / 32), dim3(32, 8)>>>(fc2_W, w2T, DFFN, DDIM);
    // 10) x1 = x + ctx @ W_o^T
    gemm_tc<false, false, true , false, false><<<dim3(DDIM / BNT, MROWS / BMT), 256, GEMM_SMEM>>>(
        ctx, wo, nullptr, x, x1, MROWS, DDIM, DDIM);
    // 11) h = round(LN2(x1))
    ln_kernel<true><<<MROWS, 256>>>(x1, ln2_g, ln2_b, h);
    // 12) f = round(gelu(h @ w1T^T + b1))
    gemm_tc<true , true , false, true , false><<<dim3(DFFN / BNT, MROWS / BMT), 256, GEMM_SMEM>>>(
        h, w1T, fc1_b, nullptr, f, MROWS, DFFN, DDIM);
    // 13) out = x1 + f @ w2T^T + b2
    gemm_tc<false, true , true , false, false><<<dim3(DDIM / BNT, MROWS / BMT), 256, GEMM_SMEM>>>(
        f, w2T, fc2_b, x1, out, MROWS, DDIM, DFFN);
}

// round 10
// speedup vs baseline: 1.0599x; 1.0599x over previous
#include <cuda_runtime.h>
#include <math.h>
#include <stdint.h>

// Problem dims (fixed)
#define BB   2
#define LL   2048
#define DDIM 1024
#define HH   16
#define DHD  64
#define DFFN 4096
#define MROWS (BB*LL)   // 4096 token rows

// ---------------------------------------------------------------------------
// Scratch (device globals; no runtime allocation allowed)
// ---------------------------------------------------------------------------
__device__ float g_h   [(size_t)MROWS * DDIM];
__device__ float g_qkv [(size_t)MROWS * DDIM * 3];   // q | k | v
__device__ float g_ctx [(size_t)MROWS * DDIM];
__device__ float g_x1  [(size_t)MROWS * DDIM];
__device__ float g_f   [(size_t)MROWS * DFFN];
// tf32-rounded weights: wqkv = [3072][1024] NT; wo NT; w1T/w2T transposed to NT
__device__ float g_wqkv[(size_t)3 * DDIM * DDIM];
__device__ float g_wo  [(size_t)DDIM * DDIM];
__device__ float g_w1T [(size_t)DFFN * DDIM];        // [N=4096][K=1024]
__device__ float g_w2T [(size_t)DDIM * DFFN];        // [N=1024][K=4096]

// ---------------------------------------------------------------------------
// PTX helpers
// ---------------------------------------------------------------------------
__device__ __forceinline__ uint32_t smem_u32(const void* p) {
    return (uint32_t)__cvta_generic_to_shared(p);
}
__device__ __forceinline__ void cp_async16(uint32_t dst, const void* src) {
    asm volatile("cp.async.cg.shared.global [%0], [%1], 16;" :: "r"(dst), "l"(src));
}
__device__ __forceinline__ void cp_commit() {
    asm volatile("cp.async.commit_group;");
}
template<int N>
__device__ __forceinline__ void cp_wait() {
    asm volatile("cp.async.wait_group %0;" :: "n"(N));
}
__device__ __forceinline__ float rna(float f) {
    uint32_t r;
    asm("cvt.rna.tf32.f32 %0, %1;" : "=r"(r) : "f"(f));
    return __uint_as_float(r);
}
__device__ __forceinline__ void mma_tf32(float* c, const uint32_t* a, const uint32_t* b) {
    asm volatile(
        "mma.sync.aligned.m16n8k8.row.col.f32.tf32.tf32.f32 "
        "{%0,%1,%2,%3},{%4,%5,%6,%7},{%8,%9},{%0,%1,%2,%3};"
        : "+f"(c[0]), "+f"(c[1]), "+f"(c[2]), "+f"(c[3])
        : "r"(a[0]), "r"(a[1]), "r"(a[2]), "r"(a[3]), "r"(b[0]), "r"(b[1]));
}
__device__ __forceinline__ void ldsm_x4(uint32_t* r, uint32_t addr) {
    asm volatile("ldmatrix.sync.aligned.m8n8.x4.shared.b16 {%0,%1,%2,%3}, [%4];"
        : "=r"(r[0]), "=r"(r[1]), "=r"(r[2]), "=r"(r[3]) : "r"(addr));
}
__device__ __forceinline__ void ldsm_x2(uint32_t* r, uint32_t addr) {
    asm volatile("ldmatrix.sync.aligned.m8n8.x2.shared.b16 {%0,%1}, [%2];"
        : "=r"(r[0]), "=r"(r[1]) : "r"(addr));
}

// ---------------------------------------------------------------------------
// Round fp32 -> tf32 (rna) elementwise, float4 per thread
// ---------------------------------------------------------------------------
__global__ void __launch_bounds__(256) round_kernel(const float* __restrict__ in,
                                                    float* __restrict__ out, int n4) {
    int i = blockIdx.x * 256 + threadIdx.x;
    if (i < n4) {
        float4 v = ((const float4*)in)[i];
        v.x = rna(v.x); v.y = rna(v.y); v.z = rna(v.z); v.w = rna(v.w);
        ((float4*)out)[i] = v;
    }
}

// ---------------------------------------------------------------------------
// Transpose + round: in[R][C] -> out[C][R] (tf32-rounded). block (32,8), grid (C/32, R/32)
// ---------------------------------------------------------------------------
__global__ void __launch_bounds__(256) roundT_kernel(const float* __restrict__ in,
                                                     float* __restrict__ out,
                                                     int R, int C) {
    __shared__ float t[32][33];
    int bx = blockIdx.x * 32, by = blockIdx.y * 32;
    int x = threadIdx.x, y = threadIdx.y;
    #pragma unroll
    for (int i = 0; i < 32; i += 8)
        t[y + i][x] = in[(size_t)(by + y + i) * C + bx + x];
    __syncthreads();
    #pragma unroll
    for (int i = 0; i < 32; i += 8)
        out[(size_t)(bx + y + i) * R + by + x] = rna(t[x][y + i]);
}

// ---------------------------------------------------------------------------
// LayerNorm; rounds output to tf32 when it feeds a GEMM A operand
// ---------------------------------------------------------------------------
template<bool RND>
__global__ void __launch_bounds__(256) ln_kernel(const float* __restrict__ x,
                                                 const float* __restrict__ g,
                                                 const float* __restrict__ b,
                                                 float* __restrict__ out) {
    int row = blockIdx.x;
    int t = threadIdx.x;
    const float4* xr = (const float4*)(x + (size_t)row * DDIM);
    float4 v = xr[t];
    __shared__ float sred[8];

    float s = v.x + v.y + v.z + v.w;
    #pragma unroll
    for (int o = 16; o > 0; o >>= 1) s += __shfl_xor_sync(0xffffffffu, s, o);
    if ((t & 31) == 0) sred[t >> 5] = s;
    __syncthreads();
    float tot = 0.f;
    #pragma unroll
    for (int w = 0; w < 8; w++) tot += sred[w];
    float mu = tot * (1.0f / DDIM);

    float dx = v.x - mu, dy = v.y - mu, dz = v.z - mu, dw = v.w - mu;
    float s2 = dx*dx + dy*dy + dz*dz + dw*dw;
    #pragma unroll
    for (int o = 16; o > 0; o >>= 1) s2 += __shfl_xor_sync(0xffffffffu, s2, o);
    __syncthreads();
    if ((t & 31) == 0) sred[t >> 5] = s2;
    __syncthreads();
    float tv = 0.f;
    #pragma unroll
    for (int w = 0; w < 8; w++) tv += sred[w];
    float rstd = rsqrtf(tv * (1.0f / DDIM) + 1e-5f);

    float4 gg = ((const float4*)g)[t];
    float4 bb = ((const float4*)b)[t];
    float4 o4;
    o4.x = dx * rstd * gg.x + bb.x;
    o4.y = dy * rstd * gg.y + bb.y;
    o4.z = dz * rstd * gg.z + bb.z;
    o4.w = dw * rstd * gg.w + bb.w;
    if (RND) { o4.x = rna(o4.x); o4.y = rna(o4.y); o4.z = rna(o4.z); o4.w = rna(o4.w); }
    ((float4*)(out + (size_t)row * DDIM))[t] = o4;
}

// ---------------------------------------------------------------------------
// tf32 tensor-core GEMM (NT): C[M,N] = A[M,K] @ B[N,K]^T
// Inputs pre-rounded tf32 -> raw-bit operands exact.
// CTA 128x128x32, 8 warps (2x4), warp 64x32, mma.m16n8k8.
// BKT=32: stage row stride 36 floats (9x16B, coprime 8 -> conflict-free),
// 3-stage cp.async ring, ONE __syncthreads per 32-wide k-tile (halved barrier
// frequency vs BKT=16). smem 108KB/CTA -> 2 CTAs/SM (reg cap anyway).
// SPLIT: C is 3 concatenated [MROWS][1024] buffers, column block selects one.
// ---------------------------------------------------------------------------
#define BMT 128
#define BNT 128
#define BKT 32
#define KSTR 36
#define NSTG 3
#define STG_F (BMT * KSTR)               // 4608 floats per stage per matrix
#define GEMM_SMEM (NSTG * STG_F * 2 * 4) // 110592 bytes

template<bool GELU, bool BIAS, bool RES, bool RND, bool SPLIT>
__global__ void __launch_bounds__(256) gemm_tc(
    const float* __restrict__ A, const float* __restrict__ Bm,
    const float* __restrict__ bias, const float* __restrict__ res,
    float* __restrict__ C, int M, int N, int K)
{
    extern __shared__ float sm[];
    float* As = sm;                  // [NSTG][4608]  ([row][k] stride 36)
    float* Bs = sm + NSTG * STG_F;   // [NSTG][4608]  ([n][k] stride 36)

    int tid  = threadIdx.x;
    int lane = tid & 31;
    int wid  = tid >> 5;
    int wm   = wid >> 2;
    int wn   = wid & 3;
    int m0 = blockIdx.y * BMT;
    int n0 = blockIdx.x * BNT;

    float acc[4][4][4];
    #pragma unroll
    for (int i = 0; i < 4; i++)
        #pragma unroll
        for (int j = 0; j < 4; j++)
            #pragma unroll
            for (int r = 0; r < 4; r++) acc[i][j][r] = 0.f;

    auto issue = [&](int st, int k0) {
        float* as = As + st * STG_F;
        float* bs = Bs + st * STG_F;
        // 128 rows x 32 floats = 1024 x 16B chunks per matrix, 4 per thread
        #pragma unroll
        for (int i = 0; i < 4; i++) {
            int idx = tid + i * 256;
            int row = idx >> 3, c = idx & 7;
            cp_async16(smem_u32(as + row * KSTR + c * 4),
                       A + (size_t)(m0 + row) * K + k0 + c * 4);
        }
        #pragma unroll
        for (int i = 0; i < 4; i++) {
            int idx = tid + i * 256;
            int row = idx >> 3, c = idx & 7;
            cp_async16(smem_u32(bs + row * KSTR + c * 4),
                       Bm + (size_t)(n0 + row) * K + k0 + c * 4);
        }
        cp_commit();
    };

    int nk = K / BKT;
    issue(0, 0);
    issue(1, BKT);

    for (int kt = 0; kt < nk; kt++) {
        if (kt + 1 < nk) cp_wait<1>(); else cp_wait<0>();
        __syncthreads();

        if (kt + 2 < nk) issue((kt + 2) % NSTG, (kt + 2) * BKT);

        const float* as = As + (kt % NSTG) * STG_F;
        const float* bs = Bs + (kt % NSTG) * STG_F;
        #pragma unroll
        for (int ks = 0; ks < 4; ks++) {
            uint32_t af[4][4], bf[4][2];
            {
                int rowbase = wm * 64 + (lane & 15);
                int koff = ks * 8 + ((lane >> 4) << 2);
                #pragma unroll
                for (int mt = 0; mt < 4; mt++)
                    ldsm_x4(af[mt], smem_u32(as + (rowbase + mt * 16) * KSTR + koff));
            }
            {
                int nb = wn * 32 + (lane & 7);
                int koff = ks * 8 + ((lane & 8) ? 4 : 0);
                #pragma unroll
                for (int nt = 0; nt < 4; nt++)
                    ldsm_x2(bf[nt], smem_u32(bs + (nb + nt * 8) * KSTR + koff));
            }
            #pragma unroll
            for (int mt = 0; mt < 4; mt++)
                #pragma unroll
                for (int nt = 0; nt < 4; nt++)
                    mma_tf32(acc[mt][nt], af[mt], bf[nt]);
        }
    }

    // ---- epilogue ----
    float* Cb = C;
    int ldc = N, ncol0 = n0;
    if (SPLIT) {
        Cb = C + (size_t)(n0 >> 10) * ((size_t)MROWS * DDIM);
        ldc = DDIM;
        ncol0 = n0 & 1023;
    }
    #pragma unroll
    for (int mt = 0; mt < 4; mt++) {
        #pragma unroll
        for (int nt = 0; nt < 4; nt++) {
            int row = m0 + wm * 64 + mt * 16 + (lane >> 2);
            int nc  = wn * 32 + nt * 8 + (lane & 3) * 2;
            int col = ncol0 + nc;
            #pragma unroll
            for (int half = 0; half < 2; half++) {
                int r = row + half * 8;
                float v0 = acc[mt][nt][half * 2 + 0];
                float v1 = acc[mt][nt][half * 2 + 1];
                if (BIAS) { v0 += bias[n0 + nc]; v1 += bias[n0 + nc + 1]; }
                if (GELU) {
                    v0 = 0.5f * v0 * (1.0f + erff(v0 * 0.70710678118654752f));
                    v1 = 0.5f * v1 * (1.0f + erff(v1 * 0.70710678118654752f));
                }
                if (RES) {
                    const float2 rr = *(const float2*)(res + (size_t)r * ldc + col);
                    v0 += rr.x; v1 += rr.y;
                }
                if (RND) { v0 = rna(v0); v1 = rna(v1); }
                float2 o2; o2.x = v0; o2.y = v1;
                *(float2*)(Cb + (size_t)r * ldc + col) = o2;
            }
        }
    }
}

// ---------------------------------------------------------------------------
// Causal flash attention with tf32 tensor cores (validated R7; unchanged)
// ---------------------------------------------------------------------------
__global__ void __launch_bounds__(256) attn_kernel(
    const float* __restrict__ Q, const float* __restrict__ K,
    const float* __restrict__ V, float* __restrict__ O) {
    __shared__ float Qs[64][68];    // [r][d]
    __shared__ float Ks[32][68];    // [c][d]
    __shared__ float Vs[64][44];    // [d][c]
    __shared__ float Ps[64][36];    // [r][c]
    __shared__ float sm_m[64], sm_l[64], sm_fc[64];

    int tid  = threadIdx.x;
    int lane = tid & 31;
    int wid  = tid >> 5;
    int mi   = wid & 3;
    int whalf = wid >> 2;
    int qt = blockIdx.x;
    int bh = blockIdx.y;
    size_t base = (size_t)(bh / HH) * LL * DDIM + (size_t)(bh % HH) * DHD;
    int q0 = qt * 64;

    #pragma unroll
    for (int i = 0; i < 4; i++) {
        int e = tid + i * 256;
        int r = e >> 4, c4 = (e & 15) * 4;
        *(float4*)&Qs[r][c4] = *(const float4*)(Q + base + (size_t)(q0 + r) * DDIM + c4);
    }
    if (tid < 64) { sm_m[tid] = -3.0e38f; sm_l[tid] = 0.f; }

    float o[4][4];
    #pragma unroll
    for (int nt = 0; nt < 4; nt++)
        #pragma unroll
        for (int r = 0; r < 4; r++) o[nt][r] = 0.f;

    int r0 = mi * 16 + (lane >> 2);
    int r1 = r0 + 8;

    int nkt = (q0 + 64) / 32;
    for (int kt = 0; kt < nkt; kt++) {
        int k0 = kt * 32;
        __syncthreads();
        #pragma unroll
        for (int i = 0; i < 2; i++) {
            int e = tid + i * 256;
            int c = e >> 4, d4 = (e & 15) * 4;
            *(float4*)&Ks[c][d4] = *(const float4*)(K + base + (size_t)(k0 + c) * DDIM + d4);
        }
        #pragma unroll
        for (int i = 0; i < 8; i++) {
            int e = tid + i * 256;
            int c = e >> 6, d = e & 63;
            Vs[d][c] = V[base + (size_t)(k0 + c) * DDIM + d];
        }
        __syncthreads();

        // S = Q K^T (64x32), warp computes 16x16
        float cs[2][4];
        #pragma unroll
        for (int nt = 0; nt < 2; nt++)
            #pragma unroll
            for (int r = 0; r < 4; r++) cs[nt][r] = 0.f;
        #pragma unroll
        for (int ks = 0; ks < 8; ks++) {
            uint32_t aq[4], bk[2][2];
            int rowQ = mi * 16 + (lane & 15);
            int koff = ks * 8 + ((lane >> 4) << 2);
            ldsm_x4(aq, smem_u32(&Qs[rowQ][0] + koff));
            int nb = whalf * 16 + (lane & 7);
            int koffb = ks * 8 + ((lane & 8) ? 4 : 0);
            ldsm_x2(bk[0], smem_u32(&Ks[nb][0] + koffb));
            ldsm_x2(bk[1], smem_u32(&Ks[nb + 8][0] + koffb));
            mma_tf32(cs[0], aq, bk[0]);
            mma_tf32(cs[1], aq, bk[1]);
        }
        {
            int cb = whalf * 16 + (lane & 3) * 2;
            #pragma unroll
            for (int nt = 0; nt < 2; nt++) {
                int c0 = cb + nt * 8;
                float s00 = cs[nt][0] * 0.125f, s01 = cs[nt][1] * 0.125f;
                float s10 = cs[nt][2] * 0.125f, s11 = cs[nt][3] * 0.125f;
                if (k0 + c0     > q0 + r0) s00 = -3.0e38f;
                if (k0 + c0 + 1 > q0 + r0) s01 = -3.0e38f;
                if (k0 + c0     > q0 + r1) s10 = -3.0e38f;
                if (k0 + c0 + 1 > q0 + r1) s11 = -3.0e38f;
                float2 t0; t0.x = s00; t0.y = s01;
                float2 t1; t1.x = s10; t1.y = s11;
                *(float2*)&Ps[r0][c0] = t0;
                *(float2*)&Ps[r1][c0] = t1;
            }
        }
        __syncthreads();

        // online softmax: 4 threads per row
        {
            int row = tid >> 2;
            int qd  = tid & 3;
            float sv[8];
            #pragma unroll
            for (int j = 0; j < 8; j++) sv[j] = Ps[row][qd * 8 + j];
            float tmax = sv[0];
            #pragma unroll
            for (int j = 1; j < 8; j++) tmax = fmaxf(tmax, sv[j]);
            tmax = fmaxf(tmax, __shfl_xor_sync(0xffffffffu, tmax, 1));
            tmax = fmaxf(tmax, __shfl_xor_sync(0xffffffffu, tmax, 2));
            float mold = sm_m[row];
            float newm = fmaxf(mold, tmax);
            float fcr  = __expf(mold - newm);
            float tsum = 0.f;
            #pragma unroll
            for (int j = 0; j < 8; j++) {
                float p = __expf(sv[j] - newm);
                tsum += p;
                sv[j] = rna(p);
            }
            #pragma unroll
            for (int j = 0; j < 8; j++) Ps[row][qd * 8 + j] = sv[j];
            tsum += __shfl_xor_sync(0xffffffffu, tsum, 1);
            tsum += __shfl_xor_sync(0xffffffffu, tsum, 2);
            if (qd == 0) {
                sm_m[row]  = newm;
                sm_l[row]  = sm_l[row] * fcr + tsum;
                sm_fc[row] = fcr;
            }
        }
        __syncthreads();

        // O = O*fc + P V
        {
            float f0 = sm_fc[r0], f1 = sm_fc[r1];
            #pragma unroll
            for (int nt = 0; nt < 4; nt++) {
                o[nt][0] *= f0; o[nt][1] *= f0;
                o[nt][2] *= f1; o[nt][3] *= f1;
            }
            #pragma unroll
            for (int ks = 0; ks < 4; ks++) {
                uint32_t ap[4], bv[4][2];
                int rowP = mi * 16 + (lane & 15);
                int koff = ks * 8 + ((lane >> 4) << 2);
                ldsm_x4(ap, smem_u32(&Ps[rowP][0] + koff));
                int nb = whalf * 32 + (lane & 7);
                int koffb = ks * 8 + ((lane & 8) ? 4 : 0);
                #pragma unroll
                for (int nt = 0; nt < 4; nt++)
                    ldsm_x2(bv[nt], smem_u32(&Vs[nb + nt * 8][0] + koffb));
                #pragma unroll
                for (int nt = 0; nt < 4; nt++)
                    mma_tf32(o[nt], ap, bv[nt]);
            }
        }
    }

    __syncthreads();
    {
        float inv0 = 1.0f / sm_l[r0];
        float inv1 = 1.0f / sm_l[r1];
        #pragma unroll
        for (int nt = 0; nt < 4; nt++) {
            int col = whalf * 32 + nt * 8 + (lane & 3) * 2;
            float2 t0, t1;
            t0.x = rna(o[nt][0] * inv0); t0.y = rna(o[nt][1] * inv0);
            t1.x = rna(o[nt][2] * inv1); t1.y = rna(o[nt][3] * inv1);
            *(float2*)(O + base + (size_t)(q0 + r0) * DDIM + col) = t0;
            *(float2*)(O + base + (size_t)(q0 + r1) * DDIM + col) = t1;
        }
    }
}

// ---------------------------------------------------------------------------
// Launch sequence
// ---------------------------------------------------------------------------
extern "C" void kernel_launch(void* const* d_in, const int* in_sizes, int n_in,
                              void* d_out, int out_size) {
    const float* x     = (const float*)d_in[0];
    const float* ln1_g = (const float*)d_in[2];
    const float* ln1_b = (const float*)d_in[3];
    const float* W_q   = (const float*)d_in[4];
    const float* W_k   = (const float*)d_in[5];
    const float* W_v   = (const float*)d_in[6];
    const float* W_o   = (const float*)d_in[7];
    const float* ln2_g = (const float*)d_in[8];
    const float* ln2_b = (const float*)d_in[9];
    const float* fc1_W = (const float*)d_in[10];
    const float* fc1_b = (const float*)d_in[11];
    const float* fc2_W = (const float*)d_in[12];
    const float* fc2_b = (const float*)d_in[13];
    float* out = (float*)d_out;

    float *h, *qkv, *ctx, *x1, *f, *wqkv, *wo, *w1T, *w2T;
    cudaGetSymbolAddress((void**)&h,    g_h);
    cudaGetSymbolAddress((void**)&qkv,  g_qkv);
    cudaGetSymbolAddress((void**)&ctx,  g_ctx);
    cudaGetSymbolAddress((void**)&x1,   g_x1);
    cudaGetSymbolAddress((void**)&f,    g_f);
    cudaGetSymbolAddress((void**)&wqkv, g_wqkv);
    cudaGetSymbolAddress((void**)&wo,   g_wo);
    cudaGetSymbolAddress((void**)&w1T,  g_w1T);
    cudaGetSymbolAddress((void**)&w2T,  g_w2T);

    float* q = qkv;
    float* k = qkv + (size_t)MROWS * DDIM;
    float* v = qkv + (size_t)2 * MROWS * DDIM;

    cudaFuncSetAttribute(gemm_tc<false, false, false, true , true >, cudaFuncAttributeMaxDynamicSharedMemorySize, GEMM_SMEM);
    cudaFuncSetAttribute(gemm_tc<false, false, true , false, false>, cudaFuncAttributeMaxDynamicSharedMemorySize, GEMM_SMEM);
    cudaFuncSetAttribute(gemm_tc<true , true , false, true , false>, cudaFuncAttributeMaxDynamicSharedMemorySize, GEMM_SMEM);
    cudaFuncSetAttribute(gemm_tc<false, true , true , false, false>, cudaFuncAttributeMaxDynamicSharedMemorySize, GEMM_SMEM);

    int nDD = DDIM * DDIM / 4;

    // round QKV weights into concatenated buffer
    round_kernel<<<(nDD + 255) / 256, 256>>>(W_q, wqkv,            nDD);
    round_kernel<<<(nDD + 255) / 256, 256>>>(W_k, wqkv + nDD * 4,  nDD);
    round_kernel<<<(nDD + 255) / 256, 256>>>(W_v, wqkv + nDD * 8,  nDD);
    // h = round(LN1(x))
    ln_kernel<true><<<MROWS, 256>>>(x, ln1_g, ln1_b, h);
    // fused qkv = round(h @ Wqkv^T), split epilogue
    gemm_tc<false, false, false, true , true ><<<dim3(3 * DDIM / BNT, MROWS / BMT), 256, GEMM_SMEM>>>(
        h, wqkv, nullptr, nullptr, qkv, MROWS, 3 * DDIM, DDIM);
    // ctx = round(attention(q,k,v))
    attn_kernel<<<dim3(LL / 64, BB * HH), 256>>>(q, k, v, ctx);
    // round W_o; transpose+round fc1_W, fc2_W into NT layout
    round_kernel<<<(nDD + 255) / 256, 256>>>(W_o, wo, nDD);
    roundT_kernel<<<dim3(DFFN / 32, DDIM / 32), dim3(32, 8)>>>(fc1_W, w1T, DDIM, DFFN);
    roundT_kernel<<<dim3(DDIM / 32, DFFN / 32), dim3(32, 8)>>>(fc2_W, w2T, DFFN, DDIM);
    // x1 = x + ctx @ W_o^T
    gemm_tc<false, false, true , false, false><<<dim3(DDIM / BNT, MROWS / BMT), 256, GEMM_SMEM>>>(
        ctx, wo, nullptr, x, x1, MROWS, DDIM, DDIM);
    // h = round(LN2(x1))
    ln_kernel<true><<<MROWS, 256>>>(x1, ln2_g, ln2_b, h);
    // f = round(gelu(h @ w1T^T + b1))
    gemm_tc<true , true , false, true , false><<<dim3(DFFN / BNT, MROWS / BMT), 256, GEMM_SMEM>>>(
        h, w1T, fc1_b, nullptr, f, MROWS, DFFN, DDIM);
    // out = x1 + f @ w2T^T + b2
    gemm_tc<false, true , true , false, false><<<dim3(DDIM / BNT, MROWS / BMT), 256, GEMM_SMEM>>>(
        f, w2T, fc2_b, x1, out, MROWS, DDIM, DFFN);
}

// round 12
// speedup vs baseline: 1.0726x; 1.0119x over previous
#include <cuda_runtime.h>
#include <math.h>
#include <stdint.h>

// Problem dims (fixed)
#define BB   2
#define LL   2048
#define DDIM 1024
#define HH   16
#define DHD  64
#define DFFN 4096
#define MROWS (BB*LL)   // 4096 token rows

// ---------------------------------------------------------------------------
// Scratch (device globals; no runtime allocation allowed)
// ---------------------------------------------------------------------------
__device__ float g_h   [(size_t)MROWS * DDIM];
__device__ float g_qkv [(size_t)MROWS * DDIM * 3];   // q | k | v
__device__ float g_ctx [(size_t)MROWS * DDIM];
__device__ float g_x1  [(size_t)MROWS * DDIM];
__device__ float g_f   [(size_t)MROWS * DFFN];
// tf32-rounded weights (all NT: [N][K])
__device__ float g_wqkv[(size_t)3 * DDIM * DDIM];
__device__ float g_wo  [(size_t)DDIM * DDIM];
__device__ float g_w1T [(size_t)DFFN * DDIM];
__device__ float g_w2T [(size_t)DDIM * DFFN];

// ---------------------------------------------------------------------------
// PTX helpers
// ---------------------------------------------------------------------------
__device__ __forceinline__ uint32_t smem_u32(const void* p) {
    return (uint32_t)__cvta_generic_to_shared(p);
}
__device__ __forceinline__ void cp_async16(uint32_t dst, const void* src) {
    asm volatile("cp.async.cg.shared.global [%0], [%1], 16;" :: "r"(dst), "l"(src));
}
__device__ __forceinline__ void cp_commit() {
    asm volatile("cp.async.commit_group;");
}
template<int N>
__device__ __forceinline__ void cp_wait() {
    asm volatile("cp.async.wait_group %0;" :: "n"(N));
}
__device__ __forceinline__ float rna(float f) {
    uint32_t r;
    asm("cvt.rna.tf32.f32 %0, %1;" : "=r"(r) : "f"(f));
    return __uint_as_float(r);
}
__device__ __forceinline__ void mma_tf32(float* c, const uint32_t* a, const uint32_t* b) {
    asm volatile(
        "mma.sync.aligned.m16n8k8.row.col.f32.tf32.tf32.f32 "
        "{%0,%1,%2,%3},{%4,%5,%6,%7},{%8,%9},{%0,%1,%2,%3};"
        : "+f"(c[0]), "+f"(c[1]), "+f"(c[2]), "+f"(c[3])
        : "r"(a[0]), "r"(a[1]), "r"(a[2]), "r"(a[3]), "r"(b[0]), "r"(b[1]));
}
__device__ __forceinline__ void ldsm_x4(uint32_t* r, uint32_t addr) {
    asm volatile("ldmatrix.sync.aligned.m8n8.x4.shared.b16 {%0,%1,%2,%3}, [%4];"
        : "=r"(r[0]), "=r"(r[1]), "=r"(r[2]), "=r"(r[3]) : "r"(addr));
}
__device__ __forceinline__ void ldsm_x2(uint32_t* r, uint32_t addr) {
    asm volatile("ldmatrix.sync.aligned.m8n8.x2.shared.b16 {%0,%1}, [%2];"
        : "=r"(r[0]), "=r"(r[1]) : "r"(addr));
}

// ---------------------------------------------------------------------------
// Round fp32 -> tf32 (rna) elementwise, float4 per thread
// ---------------------------------------------------------------------------
__global__ void __launch_bounds__(256) round_kernel(const float* __restrict__ in,
                                                    float* __restrict__ out, int n4) {
    int i = blockIdx.x * 256 + threadIdx.x;
    if (i < n4) {
        float4 v = ((const float4*)in)[i];
        v.x = rna(v.x); v.y = rna(v.y); v.z = rna(v.z); v.w = rna(v.w);
        ((float4*)out)[i] = v;
    }
}

// ---------------------------------------------------------------------------
// Transpose + round: in[R][C] -> out[C][R] (tf32). block (32,8)
// ---------------------------------------------------------------------------
__global__ void __launch_bounds__(256) roundT_kernel(const float* __restrict__ in,
                                                     float* __restrict__ out,
                                                     int R, int C) {
    __shared__ float t[32][33];
    int bx = blockIdx.x * 32, by = blockIdx.y * 32;
    int x = threadIdx.x, y = threadIdx.y;
    #pragma unroll
    for (int i = 0; i < 32; i += 8)
        t[y + i][x] = in[(size_t)(by + y + i) * C + bx + x];
    __syncthreads();
    #pragma unroll
    for (int i = 0; i < 32; i += 8)
        out[(size_t)(bx + y + i) * R + by + x] = rna(t[x][y + i]);
}

// ---------------------------------------------------------------------------
// LayerNorm (validated)
// ---------------------------------------------------------------------------
template<bool RND>
__global__ void __launch_bounds__(256) ln_kernel(const float* __restrict__ x,
                                                 const float* __restrict__ g,
                                                 const float* __restrict__ b,
                                                 float* __restrict__ out) {
    int row = blockIdx.x;
    int t = threadIdx.x;
    const float4* xr = (const float4*)(x + (size_t)row * DDIM);
    float4 v = xr[t];
    __shared__ float sred[8];

    float s = v.x + v.y + v.z + v.w;
    #pragma unroll
    for (int o = 16; o > 0; o >>= 1) s += __shfl_xor_sync(0xffffffffu, s, o);
    if ((t & 31) == 0) sred[t >> 5] = s;
    __syncthreads();
    float tot = 0.f;
    #pragma unroll
    for (int w = 0; w < 8; w++) tot += sred[w];
    float mu = tot * (1.0f / DDIM);

    float dx = v.x - mu, dy = v.y - mu, dz = v.z - mu, dw = v.w - mu;
    float s2 = dx*dx + dy*dy + dz*dz + dw*dw;
    #pragma unroll
    for (int o = 16; o > 0; o >>= 1) s2 += __shfl_xor_sync(0xffffffffu, s2, o);
    __syncthreads();
    if ((t & 31) == 0) sred[t >> 5] = s2;
    __syncthreads();
    float tv = 0.f;
    #pragma unroll
    for (int w = 0; w < 8; w++) tv += sred[w];
    float rstd = rsqrtf(tv * (1.0f / DDIM) + 1e-5f);

    float4 gg = ((const float4*)g)[t];
    float4 bb = ((const float4*)b)[t];
    float4 o4;
    o4.x = dx * rstd * gg.x + bb.x;
    o4.y = dy * rstd * gg.y + bb.y;
    o4.z = dz * rstd * gg.z + bb.z;
    o4.w = dw * rstd * gg.w + bb.w;
    if (RND) { o4.x = rna(o4.x); o4.y = rna(o4.y); o4.z = rna(o4.z); o4.w = rna(o4.w); }
    ((float4*)(out + (size_t)row * DDIM))[t] = o4;
}

// ---------------------------------------------------------------------------
// tf32 tensor-core GEMM (NT): C[M,N] = A[M,K] @ B[N,K]^T  (validated R10)
// CTA 128x128x32, 8 warps (2x4), warp 64x32, mma.m16n8k8, stride-36 smem,
// 3-stage cp.async ring, one __syncthreads per 32-wide k-tile.
// ---------------------------------------------------------------------------
#define BMT 128
#define BNT 128
#define BKT 32
#define KSTR 36
#define NSTG 3
#define STG_F (BMT * KSTR)               // 4608 floats per stage per matrix
#define GEMM_SMEM (NSTG * STG_F * 2 * 4) // 110592 bytes

template<bool GELU, bool BIAS, bool RES, bool RND, bool SPLIT>
__global__ void __launch_bounds__(256) gemm_tc(
    const float* __restrict__ A, const float* __restrict__ Bm,
    const float* __restrict__ bias, const float* __restrict__ res,
    float* __restrict__ C, int M, int N, int K)
{
    extern __shared__ float sm[];
    float* As = sm;
    float* Bs = sm + NSTG * STG_F;

    int tid  = threadIdx.x;
    int lane = tid & 31;
    int wid  = tid >> 5;
    int wm   = wid >> 2;
    int wn   = wid & 3;
    int m0 = blockIdx.y * BMT;
    int n0 = blockIdx.x * BNT;

    float acc[4][4][4];
    #pragma unroll
    for (int i = 0; i < 4; i++)
        #pragma unroll
        for (int j = 0; j < 4; j++)
            #pragma unroll
            for (int r = 0; r < 4; r++) acc[i][j][r] = 0.f;

    auto issue = [&](int st, int k0) {
        float* as = As + st * STG_F;
        float* bs = Bs + st * STG_F;
        #pragma unroll
        for (int i = 0; i < 4; i++) {
            int idx = tid + i * 256;
            int row = idx >> 3, c = idx & 7;
            cp_async16(smem_u32(as + row * KSTR + c * 4),
                       A + (size_t)(m0 + row) * K + k0 + c * 4);
        }
        #pragma unroll
        for (int i = 0; i < 4; i++) {
            int idx = tid + i * 256;
            int row = idx >> 3, c = idx & 7;
            cp_async16(smem_u32(bs + row * KSTR + c * 4),
                       Bm + (size_t)(n0 + row) * K + k0 + c * 4);
        }
        cp_commit();
    };

    int nk = K / BKT;
    issue(0, 0);
    issue(1, BKT);

    for (int kt = 0; kt < nk; kt++) {
        if (kt + 1 < nk) cp_wait<1>(); else cp_wait<0>();
        __syncthreads();

        if (kt + 2 < nk) issue((kt + 2) % NSTG, (kt + 2) * BKT);

        const float* as = As + (kt % NSTG) * STG_F;
        const float* bs = Bs + (kt % NSTG) * STG_F;
        #pragma unroll
        for (int ks = 0; ks < 4; ks++) {
            uint32_t af[4][4], bf[4][2];
            {
                int rowbase = wm * 64 + (lane & 15);
                int koff = ks * 8 + ((lane >> 4) << 2);
                #pragma unroll
                for (int mt = 0; mt < 4; mt++)
                    ldsm_x4(af[mt], smem_u32(as + (rowbase + mt * 16) * KSTR + koff));
            }
            {
                int nb = wn * 32 + (lane & 7);
                int koff = ks * 8 + ((lane & 8) ? 4 : 0);
                #pragma unroll
                for (int nt = 0; nt < 4; nt++)
                    ldsm_x2(bf[nt], smem_u32(bs + (nb + nt * 8) * KSTR + koff));
            }
            #pragma unroll
            for (int mt = 0; mt < 4; mt++)
                #pragma unroll
                for (int nt = 0; nt < 4; nt++)
                    mma_tf32(acc[mt][nt], af[mt], bf[nt]);
        }
    }

    // ---- epilogue ----
    float* Cb = C;
    int ldc = N, ncol0 = n0;
    if (SPLIT) {
        Cb = C + (size_t)(n0 >> 10) * ((size_t)MROWS * DDIM);
        ldc = DDIM;
        ncol0 = n0 & 1023;
    }
    #pragma unroll
    for (int mt = 0; mt < 4; mt++) {
        #pragma unroll
        for (int nt = 0; nt < 4; nt++) {
            int row = m0 + wm * 64 + mt * 16 + (lane >> 2);
            int nc  = wn * 32 + nt * 8 + (lane & 3) * 2;
            int col = ncol0 + nc;
            #pragma unroll
            for (int half = 0; half < 2; half++) {
                int r = row + half * 8;
                float v0 = acc[mt][nt][half * 2 + 0];
                float v1 = acc[mt][nt][half * 2 + 1];
                if (BIAS) { v0 += bias[n0 + nc]; v1 += bias[n0 + nc + 1]; }
                if (GELU) {
                    v0 = 0.5f * v0 * (1.0f + erff(v0 * 0.70710678118654752f));
                    v1 = 0.5f * v1 * (1.0f + erff(v1 * 0.70710678118654752f));
                }
                if (RES) {
                    const float2 rr = *(const float2*)(res + (size_t)r * ldc + col);
                    v0 += rr.x; v1 += rr.y;
                }
                if (RND) { v0 = rna(v0); v1 = rna(v1); }
                float2 o2; o2.x = v0; o2.y = v1;
                *(float2*)(Cb + (size_t)r * ldc + col) = o2;
            }
        }
    }
}

// ---------------------------------------------------------------------------
// Causal flash attention, tf32 mma.sync, q-tile 128 (was 64).
// 8 warps; warp w owns rows w*16..w*16+15.
//  S:  128x32 per kv-tile; warp computes 16x32 (4 n8 tiles)
//  PV: O 128x64; warp computes 16x64 (8 n8 tiles)
// Softmax: 2 threads/row, 16 cols each.
// Dynamic smem (73 KB): Qs[128][68] Ks[32][68] Vs[64][44] Ps[128][36] m/l/fc[128]
// ---------------------------------------------------------------------------
#define QS_OFF 0
#define KS_OFF 8704
#define VS_OFF 10880
#define PS_OFF 13696
#define SMM_OFF 18304
#define SML_OFF 18432
#define SMF_OFF 18560
#define ATTN_SMEM (18688 * 4)

__global__ void __launch_bounds__(256) attn_kernel(
    const float* __restrict__ Q, const float* __restrict__ K,
    const float* __restrict__ V, float* __restrict__ O) {
    extern __shared__ float smf[];
    float* Qs = smf + QS_OFF;    // [r][d] stride 68
    float* Ks = smf + KS_OFF;    // [c][d] stride 68
    float* Vs = smf + VS_OFF;    // [d][c] stride 44
    float* Ps = smf + PS_OFF;    // [r][c] stride 36
    float* sm_m  = smf + SMM_OFF;
    float* sm_l  = smf + SML_OFF;
    float* sm_fc = smf + SMF_OFF;

    int tid  = threadIdx.x;
    int lane = tid & 31;
    int wid  = tid >> 5;          // 0..7: row band
    int qt = blockIdx.x;
    int bh = blockIdx.y;
    size_t base = (size_t)(bh / HH) * LL * DDIM + (size_t)(bh % HH) * DHD;
    int q0 = qt * 128;

    // Load Q tile [128][64] (float4 coalesced)
    #pragma unroll
    for (int i = 0; i < 8; i++) {
        int e = tid + i * 256;              // 0..2047
        int r = e >> 4, c4 = (e & 15) * 4;
        *(float4*)&Qs[r * 68 + c4] = *(const float4*)(Q + base + (size_t)(q0 + r) * DDIM + c4);
    }
    if (tid < 128) { sm_m[tid] = -3.0e38f; sm_l[tid] = 0.f; }

    float o[8][4];
    #pragma unroll
    for (int nt = 0; nt < 8; nt++)
        #pragma unroll
        for (int r = 0; r < 4; r++) o[nt][r] = 0.f;

    int r0 = wid * 16 + (lane >> 2);
    int r1 = r0 + 8;

    int nkt = (q0 + 128) / 32;
    for (int kt = 0; kt < nkt; kt++) {
        int k0 = kt * 32;
        __syncthreads();
        // K: [32][64]
        #pragma unroll
        for (int i = 0; i < 2; i++) {
            int e = tid + i * 256;
            int c = e >> 4, d4 = (e & 15) * 4;
            *(float4*)&Ks[c * 68 + d4] = *(const float4*)(K + base + (size_t)(k0 + c) * DDIM + d4);
        }
        // V transposed: Vs[d][c]
        #pragma unroll
        for (int i = 0; i < 8; i++) {
            int e = tid + i * 256;
            int c = e >> 6, d = e & 63;
            Vs[d * 44 + c] = V[base + (size_t)(k0 + c) * DDIM + d];
        }
        __syncthreads();

        // ---- S = Q K^T : warp computes 16 rows x 32 cols (4 n8 tiles) ----
        float cs[4][4];
        #pragma unroll
        for (int nt = 0; nt < 4; nt++)
            #pragma unroll
            for (int r = 0; r < 4; r++) cs[nt][r] = 0.f;
        #pragma unroll
        for (int ks = 0; ks < 8; ks++) {
            uint32_t aq[4], bk[4][2];
            int rowQ = wid * 16 + (lane & 15);
            int koff = ks * 8 + ((lane >> 4) << 2);
            ldsm_x4(aq, smem_u32(Qs + rowQ * 68 + koff));
            int nb = lane & 7;
            int koffb = ks * 8 + ((lane & 8) ? 4 : 0);
            #pragma unroll
            for (int nt = 0; nt < 4; nt++)
                ldsm_x2(bk[nt], smem_u32(Ks + (nb + nt * 8) * 68 + koffb));
            #pragma unroll
            for (int nt = 0; nt < 4; nt++)
                mma_tf32(cs[nt], aq, bk[nt]);
        }
        // scale, mask, store S -> Ps
        {
            int cb = (lane & 3) * 2;
            #pragma unroll
            for (int nt = 0; nt < 4; nt++) {
                int c0 = cb + nt * 8;
                float s00 = cs[nt][0] * 0.125f, s01 = cs[nt][1] * 0.125f;
                float s10 = cs[nt][2] * 0.125f, s11 = cs[nt][3] * 0.125f;
                if (k0 + c0     > q0 + r0) s00 = -3.0e38f;
                if (k0 + c0 + 1 > q0 + r0) s01 = -3.0e38f;
                if (k0 + c0     > q0 + r1) s10 = -3.0e38f;
                if (k0 + c0 + 1 > q0 + r1) s11 = -3.0e38f;
                float2 t0; t0.x = s00; t0.y = s01;
                float2 t1; t1.x = s10; t1.y = s11;
                *(float2*)&Ps[r0 * 36 + c0] = t0;
                *(float2*)&Ps[r1 * 36 + c0] = t1;
            }
        }
        __syncthreads();

        // ---- online softmax: 2 threads/row, 16 cols each ----
        {
            int row = tid >> 1;
            int qd  = tid & 1;
            float sv[16];
            #pragma unroll
            for (int j = 0; j < 16; j++) sv[j] = Ps[row * 36 + qd * 16 + j];
            float tmax = sv[0];
            #pragma unroll
            for (int j = 1; j < 16; j++) tmax = fmaxf(tmax, sv[j]);
            tmax = fmaxf(tmax, __shfl_xor_sync(0xffffffffu, tmax, 1));
            float mold = sm_m[row];
            float newm = fmaxf(mold, tmax);
            float fcr  = __expf(mold - newm);
            float tsum = 0.f;
            #pragma unroll
            for (int j = 0; j < 16; j++) {
                float p = __expf(sv[j] - newm);
                tsum += p;
                sv[j] = rna(p);
            }
            #pragma unroll
            for (int j = 0; j < 16; j++) Ps[row * 36 + qd * 16 + j] = sv[j];
            tsum += __shfl_xor_sync(0xffffffffu, tsum, 1);
            if (qd == 0) {
                sm_m[row]  = newm;
                sm_l[row]  = sm_l[row] * fcr + tsum;
                sm_fc[row] = fcr;
            }
        }
        __syncthreads();

        // ---- O = O*fc + P V : warp computes 16 rows x 64 cols (8 n8 tiles) ----
        {
            float f0 = sm_fc[r0], f1 = sm_fc[r1];
            #pragma unroll
            for (int nt = 0; nt < 8; nt++) {
                o[nt][0] *= f0; o[nt][1] *= f0;
                o[nt][2] *= f1; o[nt][3] *= f1;
            }
            #pragma unroll
            for (int ks = 0; ks < 4; ks++) {
                uint32_t ap[4], bv[8][2];
                int rowP = wid * 16 + (lane & 15);
                int koff = ks * 8 + ((lane >> 4) << 2);
                ldsm_x4(ap, smem_u32(Ps + rowP * 36 + koff));
                int nb = lane & 7;
                int koffb = ks * 8 + ((lane & 8) ? 4 : 0);
                #pragma unroll
                for (int nt = 0; nt < 8; nt++)
                    ldsm_x2(bv[nt], smem_u32(Vs + (nb + nt * 8) * 44 + koffb));
                #pragma unroll
                for (int nt = 0; nt < 8; nt++)
                    mma_tf32(o[nt], ap, bv[nt]);
            }
        }
    }

    __syncthreads();
    // epilogue
    {
        float inv0 = 1.0f / sm_l[r0];
        float inv1 = 1.0f / sm_l[r1];
        #pragma unroll
        for (int nt = 0; nt < 8; nt++) {
            int col = nt * 8 + (lane & 3) * 2;
            float2 t0, t1;
            t0.x = rna(o[nt][0] * inv0); t0.y = rna(o[nt][1] * inv0);
            t1.x = rna(o[nt][2] * inv1); t1.y = rna(o[nt][3] * inv1);
            *(float2*)(O + base + (size_t)(q0 + r0) * DDIM + col) = t0;
            *(float2*)(O + base + (size_t)(q0 + r1) * DDIM + col) = t1;
        }
    }
}

// ---------------------------------------------------------------------------
// Launch sequence
// ---------------------------------------------------------------------------
extern "C" void kernel_launch(void* const* d_in, const int* in_sizes, int n_in,
                              void* d_out, int out_size) {
    const float* x     = (const float*)d_in[0];
    const float* ln1_g = (const float*)d_in[2];
    const float* ln1_b = (const float*)d_in[3];
    const float* W_q   = (const float*)d_in[4];
    const float* W_k   = (const float*)d_in[5];
    const float* W_v   = (const float*)d_in[6];
    const float* W_o   = (const float*)d_in[7];
    const float* ln2_g = (const float*)d_in[8];
    const float* ln2_b = (const float*)d_in[9];
    const float* fc1_W = (const float*)d_in[10];
    const float* fc1_b = (const float*)d_in[11];
    const float* fc2_W = (const float*)d_in[12];
    const float* fc2_b = (const float*)d_in[13];
    float* out = (float*)d_out;

    float *h, *qkv, *ctx, *x1, *f, *wqkv, *wo, *w1T, *w2T;
    cudaGetSymbolAddress((void**)&h,    g_h);
    cudaGetSymbolAddress((void**)&qkv,  g_qkv);
    cudaGetSymbolAddress((void**)&ctx,  g_ctx);
    cudaGetSymbolAddress((void**)&x1,   g_x1);
    cudaGetSymbolAddress((void**)&f,    g_f);
    cudaGetSymbolAddress((void**)&wqkv, g_wqkv);
    cudaGetSymbolAddress((void**)&wo,   g_wo);
    cudaGetSymbolAddress((void**)&w1T,  g_w1T);
    cudaGetSymbolAddress((void**)&w2T,  g_w2T);

    float* q = qkv;
    float* k = qkv + (size_t)MROWS * DDIM;
    float* v = qkv + (size_t)2 * MROWS * DDIM;

    cudaFuncSetAttribute(gemm_tc<false, false, false, true , true >, cudaFuncAttributeMaxDynamicSharedMemorySize, GEMM_SMEM);
    cudaFuncSetAttribute(gemm_tc<false, false, true , false, false>, cudaFuncAttributeMaxDynamicSharedMemorySize, GEMM_SMEM);
    cudaFuncSetAttribute(gemm_tc<true , true , false, true , false>, cudaFuncAttributeMaxDynamicSharedMemorySize, GEMM_SMEM);
    cudaFuncSetAttribute(gemm_tc<false, true , true , false, false>, cudaFuncAttributeMaxDynamicSharedMemorySize, GEMM_SMEM);
    cudaFuncSetAttribute(attn_kernel, cudaFuncAttributeMaxDynamicSharedMemorySize, ATTN_SMEM);

    int nDD = DDIM * DDIM / 4;

    round_kernel<<<(nDD + 255) / 256, 256>>>(W_q, wqkv,           nDD);
    round_kernel<<<(nDD + 255) / 256, 256>>>(W_k, wqkv + nDD * 4, nDD);
    round_kernel<<<(nDD + 255) / 256, 256>>>(W_v, wqkv + nDD * 8, nDD);
    ln_kernel<true><<<MROWS, 256>>>(x, ln1_g, ln1_b, h);
    // fused qkv = round(h @ Wqkv^T), split epilogue
    gemm_tc<false, false, false, true , true ><<<dim3(3 * DDIM / BNT, MROWS / BMT), 256, GEMM_SMEM>>>(
        h, wqkv, nullptr, nullptr, qkv, MROWS, 3 * DDIM, DDIM);
    // ctx = round(attention(q,k,v))   q-tile 128
    attn_kernel<<<dim3(LL / 128, BB * HH), 256, ATTN_SMEM>>>(q, k, v, ctx);
    round_kernel<<<(nDD + 255) / 256, 256>>>(W_o, wo, nDD);
    roundT_kernel<<<dim3(DFFN / 32, DDIM / 32), dim3(32, 8)>>>(fc1_W, w1T, DDIM, DFFN);
    roundT_kernel<<<dim3(DDIM / 32, DFFN / 32), dim3(32, 8)>>>(fc2_W, w2T, DFFN, DDIM);
    // x1 = x + ctx @ W_o^T
    gemm_tc<false, false, true , false, false><<<dim3(DDIM / BNT, MROWS / BMT), 256, GEMM_SMEM>>>(
        ctx, wo, nullptr, x, x1, MROWS, DDIM, DDIM);
    ln_kernel<true><<<MROWS, 256>>>(x1, ln2_g, ln2_b, h);
    // f = round(gelu(h @ w1T^T + b1))
    gemm_tc<true , true , false, true , false><<<dim3(DFFN / BNT, MROWS / BMT), 256, GEMM_SMEM>>>(
        h, w1T, fc1_b, nullptr, f, MROWS, DFFN, DDIM);
    // out = x1 + f @ w2T^T + b2
    gemm_tc<false, true , true , false, false><<<dim3(DDIM / BNT, MROWS / BMT), 256, GEMM_SMEM>>>(
        f, w2T, fc2_b, x1, out, MROWS, DDIM, DFFN);
}

// round 14
// speedup vs baseline: 1.1120x; 1.0368x over previous
#include <cuda_runtime.h>
#include <math.h>
#include <stdint.h>

// Problem dims (fixed)
#define BB   2
#define LL   2048
#define DDIM 1024
#define HH   16
#define DHD  64
#define DFFN 4096
#define MROWS (BB*LL)   // 4096 token rows

// ---------------------------------------------------------------------------
// Scratch (device globals; no runtime allocation allowed)
// ---------------------------------------------------------------------------
__device__ float g_h   [(size_t)MROWS * DDIM];
__device__ float g_qkv [(size_t)MROWS * DDIM * 3];   // q | k | v
__device__ float g_ctx [(size_t)MROWS * DDIM];
__device__ float g_x1  [(size_t)MROWS * DDIM];
__device__ float g_f   [(size_t)MROWS * DFFN];
// tf32-rounded weights (all NT: [N][K])
__device__ float g_wqkv[(size_t)3 * DDIM * DDIM];
__device__ float g_wo  [(size_t)DDIM * DDIM];
__device__ float g_w1T [(size_t)DFFN * DDIM];
__device__ float g_w2T [(size_t)DDIM * DFFN];

// ---------------------------------------------------------------------------
// PTX helpers
// ---------------------------------------------------------------------------
__device__ __forceinline__ uint32_t smem_u32(const void* p) {
    return (uint32_t)__cvta_generic_to_shared(p);
}
__device__ __forceinline__ void cp_async16(uint32_t dst, const void* src) {
    asm volatile("cp.async.cg.shared.global [%0], [%1], 16;" :: "r"(dst), "l"(src));
}
__device__ __forceinline__ void cp_commit() {
    asm volatile("cp.async.commit_group;");
}
template<int N>
__device__ __forceinline__ void cp_wait() {
    asm volatile("cp.async.wait_group %0;" :: "n"(N));
}
__device__ __forceinline__ float rna(float f) {
    uint32_t r;
    asm("cvt.rna.tf32.f32 %0, %1;" : "=r"(r) : "f"(f));
    return __uint_as_float(r);
}
__device__ __forceinline__ void mma_tf32(float* c, const uint32_t* a, const uint32_t* b) {
    asm volatile(
        "mma.sync.aligned.m16n8k8.row.col.f32.tf32.tf32.f32 "
        "{%0,%1,%2,%3},{%4,%5,%6,%7},{%8,%9},{%0,%1,%2,%3};"
        : "+f"(c[0]), "+f"(c[1]), "+f"(c[2]), "+f"(c[3])
        : "r"(a[0]), "r"(a[1]), "r"(a[2]), "r"(a[3]), "r"(b[0]), "r"(b[1]));
}
__device__ __forceinline__ void ldsm_x4(uint32_t* r, uint32_t addr) {
    asm volatile("ldmatrix.sync.aligned.m8n8.x4.shared.b16 {%0,%1,%2,%3}, [%4];"
        : "=r"(r[0]), "=r"(r[1]), "=r"(r[2]), "=r"(r[3]) : "r"(addr));
}
__device__ __forceinline__ void ldsm_x2(uint32_t* r, uint32_t addr) {
    asm volatile("ldmatrix.sync.aligned.m8n8.x2.shared.b16 {%0,%1}, [%2];"
        : "=r"(r[0]), "=r"(r[1]) : "r"(addr));
}

// ---------------------------------------------------------------------------
// Round fp32 -> tf32 (rna) elementwise, float4 per thread
// ---------------------------------------------------------------------------
__global__ void __launch_bounds__(256) round_kernel(const float* __restrict__ in,
                                                    float* __restrict__ out, int n4) {
    int i = blockIdx.x * 256 + threadIdx.x;
    if (i < n4) {
        float4 v = ((const float4*)in)[i];
        v.x = rna(v.x); v.y = rna(v.y); v.z = rna(v.z); v.w = rna(v.w);
        ((float4*)out)[i] = v;
    }
}

// ---------------------------------------------------------------------------
// Transpose + round: in[R][C] -> out[C][R] (tf32). block (32,8)
// ---------------------------------------------------------------------------
__global__ void __launch_bounds__(256) roundT_kernel(const float* __restrict__ in,
                                                     float* __restrict__ out,
                                                     int R, int C) {
    __shared__ float t[32][33];
    int bx = blockIdx.x * 32, by = blockIdx.y * 32;
    int x = threadIdx.x, y = threadIdx.y;
    #pragma unroll
    for (int i = 0; i < 32; i += 8)
        t[y + i][x] = in[(size_t)(by + y + i) * C + bx + x];
    __syncthreads();
    #pragma unroll
    for (int i = 0; i < 32; i += 8)
        out[(size_t)(bx + y + i) * R + by + x] = rna(t[x][y + i]);
}

// ---------------------------------------------------------------------------
// LayerNorm (validated)
// ---------------------------------------------------------------------------
template<bool RND>
__global__ void __launch_bounds__(256) ln_kernel(const float* __restrict__ x,
                                                 const float* __restrict__ g,
                                                 const float* __restrict__ b,
                                                 float* __restrict__ out) {
    int row = blockIdx.x;
    int t = threadIdx.x;
    const float4* xr = (const float4*)(x + (size_t)row * DDIM);
    float4 v = xr[t];
    __shared__ float sred[8];

    float s = v.x + v.y + v.z + v.w;
    #pragma unroll
    for (int o = 16; o > 0; o >>= 1) s += __shfl_xor_sync(0xffffffffu, s, o);
    if ((t & 31) == 0) sred[t >> 5] = s;
    __syncthreads();
    float tot = 0.f;
    #pragma unroll
    for (int w = 0; w < 8; w++) tot += sred[w];
    float mu = tot * (1.0f / DDIM);

    float dx = v.x - mu, dy = v.y - mu, dz = v.z - mu, dw = v.w - mu;
    float s2 = dx*dx + dy*dy + dz*dz + dw*dw;
    #pragma unroll
    for (int o = 16; o > 0; o >>= 1) s2 += __shfl_xor_sync(0xffffffffu, s2, o);
    __syncthreads();
    if ((t & 31) == 0) sred[t >> 5] = s2;
    __syncthreads();
    float tv = 0.f;
    #pragma unroll
    for (int w = 0; w < 8; w++) tv += sred[w];
    float rstd = rsqrtf(tv * (1.0f / DDIM) + 1e-5f);

    float4 gg = ((const float4*)g)[t];
    float4 bb = ((const float4*)b)[t];
    float4 o4;
    o4.x = dx * rstd * gg.x + bb.x;
    o4.y = dy * rstd * gg.y + bb.y;
    o4.z = dz * rstd * gg.z + bb.z;
    o4.w = dw * rstd * gg.w + bb.w;
    if (RND) { o4.x = rna(o4.x); o4.y = rna(o4.y); o4.z = rna(o4.z); o4.w = rna(o4.w); }
    ((float4*)(out + (size_t)row * DDIM))[t] = o4;
}

// ---------------------------------------------------------------------------
// tf32 tensor-core GEMM (NT): C[M,N] = A[M,K] @ B[N,K]^T
// CTA 128x128x32, **4 warps (2x2), warp tile 64x64** (CUTLASS-style fat tile:
// 32 independent MMAs per k8 step -> deep ILP to hide ldsm/mma latency).
// Stride-36 smem, 3-stage cp.async ring, one __syncthreads per k-tile.
// acc 128 regs/thread; ~190 total -> 2 CTAs/SM (8 warps, deep chains).
// ---------------------------------------------------------------------------
#define BMT 128
#define BNT 128
#define BKT 32
#define KSTR 36
#define NSTG 3
#define STG_F (BMT * KSTR)               // 4608 floats per stage per matrix
#define GEMM_SMEM (NSTG * STG_F * 2 * 4) // 110592 bytes
#define GTHREADS 128

template<bool GELU, bool BIAS, bool RES, bool RND, bool SPLIT>
__global__ void __launch_bounds__(GTHREADS) gemm_tc(
    const float* __restrict__ A, const float* __restrict__ Bm,
    const float* __restrict__ bias, const float* __restrict__ res,
    float* __restrict__ C, int M, int N, int K)
{
    extern __shared__ float sm[];
    float* As = sm;
    float* Bs = sm + NSTG * STG_F;

    int tid  = threadIdx.x;
    int lane = tid & 31;
    int wid  = tid >> 5;       // 0..3
    int wm   = wid >> 1;       // 0..1 (64-row band)
    int wn   = wid & 1;        // 0..1 (64-col band)
    int m0 = blockIdx.y * BMT;
    int n0 = blockIdx.x * BNT;

    float acc[4][8][4];
    #pragma unroll
    for (int i = 0; i < 4; i++)
        #pragma unroll
        for (int j = 0; j < 8; j++)
            #pragma unroll
            for (int r = 0; r < 4; r++) acc[i][j][r] = 0.f;

    auto issue = [&](int st, int k0) {
        float* as = As + st * STG_F;
        float* bs = Bs + st * STG_F;
        #pragma unroll
        for (int i = 0; i < 8; i++) {
            int idx = tid + i * GTHREADS;
            int row = idx >> 3, c = idx & 7;
            cp_async16(smem_u32(as + row * KSTR + c * 4),
                       A + (size_t)(m0 + row) * K + k0 + c * 4);
        }
        #pragma unroll
        for (int i = 0; i < 8; i++) {
            int idx = tid + i * GTHREADS;
            int row = idx >> 3, c = idx & 7;
            cp_async16(smem_u32(bs + row * KSTR + c * 4),
                       Bm + (size_t)(n0 + row) * K + k0 + c * 4);
        }
        cp_commit();
    };

    int nk = K / BKT;
    issue(0, 0);
    issue(1, BKT);

    for (int kt = 0; kt < nk; kt++) {
        if (kt + 1 < nk) cp_wait<1>(); else cp_wait<0>();
        __syncthreads();

        if (kt + 2 < nk) issue((kt + 2) % NSTG, (kt + 2) * BKT);

        const float* as = As + (kt % NSTG) * STG_F;
        const float* bs = Bs + (kt % NSTG) * STG_F;
        #pragma unroll
        for (int ks = 0; ks < 4; ks++) {
            uint32_t af[4][4], bf[8][2];
            {
                int rowbase = wm * 64 + (lane & 15);
                int koff = ks * 8 + ((lane >> 4) << 2);
                #pragma unroll
                for (int mt = 0; mt < 4; mt++)
                    ldsm_x4(af[mt], smem_u32(as + (rowbase + mt * 16) * KSTR + koff));
            }
            {
                int nb = wn * 64 + (lane & 7);
                int koff = ks * 8 + ((lane & 8) ? 4 : 0);
                #pragma unroll
                for (int nt = 0; nt < 8; nt++)
                    ldsm_x2(bf[nt], smem_u32(bs + (nb + nt * 8) * KSTR + koff));
            }
            #pragma unroll
            for (int mt = 0; mt < 4; mt++)
                #pragma unroll
                for (int nt = 0; nt < 8; nt++)
                    mma_tf32(acc[mt][nt], af[mt], bf[nt]);
        }
    }

    // ---- epilogue ----
    float* Cb = C;
    int ldc = N, ncol0 = n0;
    if (SPLIT) {
        Cb = C + (size_t)(n0 >> 10) * ((size_t)MROWS * DDIM);
        ldc = DDIM;
        ncol0 = n0 & 1023;
    }
    #pragma unroll
    for (int mt = 0; mt < 4; mt++) {
        #pragma unroll
        for (int nt = 0; nt < 8; nt++) {
            int row = m0 + wm * 64 + mt * 16 + (lane >> 2);
            int nc  = wn * 64 + nt * 8 + (lane & 3) * 2;
            int col = ncol0 + nc;
            #pragma unroll
            for (int half = 0; half < 2; half++) {
                int r = row + half * 8;
                float v0 = acc[mt][nt][half * 2 + 0];
                float v1 = acc[mt][nt][half * 2 + 1];
                if (BIAS) { v0 += bias[n0 + nc]; v1 += bias[n0 + nc + 1]; }
                if (GELU) {
                    v0 = 0.5f * v0 * (1.0f + erff(v0 * 0.70710678118654752f));
                    v1 = 0.5f * v1 * (1.0f + erff(v1 * 0.70710678118654752f));
                }
                if (RES) {
                    const float2 rr = *(const float2*)(res + (size_t)r * ldc + col);
                    v0 += rr.x; v1 += rr.y;
                }
                if (RND) { v0 = rna(v0); v1 = rna(v1); }
                float2 o2; o2.x = v0; o2.y = v1;
                *(float2*)(Cb + (size_t)r * ldc + col) = o2;
            }
        }
    }
}

// ---------------------------------------------------------------------------
// Causal flash attention, tf32 mma.sync, q-tile 128 (validated R12; unchanged)
// ---------------------------------------------------------------------------
#define QS_OFF 0
#define KS_OFF 8704
#define VS_OFF 10880
#define PS_OFF 13696
#define SMM_OFF 18304
#define SML_OFF 18432
#define SMF_OFF 18560
#define ATTN_SMEM (18688 * 4)

__global__ void __launch_bounds__(256) attn_kernel(
    const float* __restrict__ Q, const float* __restrict__ K,
    const float* __restrict__ V, float* __restrict__ O) {
    extern __shared__ float smf[];
    float* Qs = smf + QS_OFF;
    float* Ks = smf + KS_OFF;
    float* Vs = smf + VS_OFF;
    float* Ps = smf + PS_OFF;
    float* sm_m  = smf + SMM_OFF;
    float* sm_l  = smf + SML_OFF;
    float* sm_fc = smf + SMF_OFF;

    int tid  = threadIdx.x;
    int lane = tid & 31;
    int wid  = tid >> 5;
    int qt = blockIdx.x;
    int bh = blockIdx.y;
    size_t base = (size_t)(bh / HH) * LL * DDIM + (size_t)(bh % HH) * DHD;
    int q0 = qt * 128;

    #pragma unroll
    for (int i = 0; i < 8; i++) {
        int e = tid + i * 256;
        int r = e >> 4, c4 = (e & 15) * 4;
        *(float4*)&Qs[r * 68 + c4] = *(const float4*)(Q + base + (size_t)(q0 + r) * DDIM + c4);
    }
    if (tid < 128) { sm_m[tid] = -3.0e38f; sm_l[tid] = 0.f; }

    float o[8][4];
    #pragma unroll
    for (int nt = 0; nt < 8; nt++)
        #pragma unroll
        for (int r = 0; r < 4; r++) o[nt][r] = 0.f;

    int r0 = wid * 16 + (lane >> 2);
    int r1 = r0 + 8;

    int nkt = (q0 + 128) / 32;
    for (int kt = 0; kt < nkt; kt++) {
        int k0 = kt * 32;
        __syncthreads();
        #pragma unroll
        for (int i = 0; i < 2; i++) {
            int e = tid + i * 256;
            int c = e >> 4, d4 = (e & 15) * 4;
            *(float4*)&Ks[c * 68 + d4] = *(const float4*)(K + base + (size_t)(k0 + c) * DDIM + d4);
        }
        #pragma unroll
        for (int i = 0; i < 8; i++) {
            int e = tid + i * 256;
            int c = e >> 6, d = e & 63;
            Vs[d * 44 + c] = V[base + (size_t)(k0 + c) * DDIM + d];
        }
        __syncthreads();

        float cs[4][4];
        #pragma unroll
        for (int nt = 0; nt < 4; nt++)
            #pragma unroll
            for (int r = 0; r < 4; r++) cs[nt][r] = 0.f;
        #pragma unroll
        for (int ks = 0; ks < 8; ks++) {
            uint32_t aq[4], bk[4][2];
            int rowQ = wid * 16 + (lane & 15);
            int koff = ks * 8 + ((lane >> 4) << 2);
            ldsm_x4(aq, smem_u32(Qs + rowQ * 68 + koff));
            int nb = lane & 7;
            int koffb = ks * 8 + ((lane & 8) ? 4 : 0);
            #pragma unroll
            for (int nt = 0; nt < 4; nt++)
                ldsm_x2(bk[nt], smem_u32(Ks + (nb + nt * 8) * 68 + koffb));
            #pragma unroll
            for (int nt = 0; nt < 4; nt++)
                mma_tf32(cs[nt], aq, bk[nt]);
        }
        {
            int cb = (lane & 3) * 2;
            #pragma unroll
            for (int nt = 0; nt < 4; nt++) {
                int c0 = cb + nt * 8;
                float s00 = cs[nt][0] * 0.125f, s01 = cs[nt][1] * 0.125f;
                float s10 = cs[nt][2] * 0.125f, s11 = cs[nt][3] * 0.125f;
                if (k0 + c0     > q0 + r0) s00 = -3.0e38f;
                if (k0 + c0 + 1 > q0 + r0) s01 = -3.0e38f;
                if (k0 + c0     > q0 + r1) s10 = -3.0e38f;
                if (k0 + c0 + 1 > q0 + r1) s11 = -3.0e38f;
                float2 t0; t0.x = s00; t0.y = s01;
                float2 t1; t1.x = s10; t1.y = s11;
                *(float2*)&Ps[r0 * 36 + c0] = t0;
                *(float2*)&Ps[r1 * 36 + c0] = t1;
            }
        }
        __syncthreads();

        {
            int row = tid >> 1;
            int qd  = tid & 1;
            float sv[16];
            #pragma unroll
            for (int j = 0; j < 16; j++) sv[j] = Ps[row * 36 + qd * 16 + j];
            float tmax = sv[0];
            #pragma unroll
            for (int j = 1; j < 16; j++) tmax = fmaxf(tmax, sv[j]);
            tmax = fmaxf(tmax, __shfl_xor_sync(0xffffffffu, tmax, 1));
            float mold = sm_m[row];
            float newm = fmaxf(mold, tmax);
            float fcr  = __expf(mold - newm);
            float tsum = 0.f;
            #pragma unroll
            for (int j = 0; j < 16; j++) {
                float p = __expf(sv[j] - newm);
                tsum += p;
                sv[j] = rna(p);
            }
            #pragma unroll
            for (int j = 0; j < 16; j++) Ps[row * 36 + qd * 16 + j] = sv[j];
            tsum += __shfl_xor_sync(0xffffffffu, tsum, 1);
            if (qd == 0) {
                sm_m[row]  = newm;
                sm_l[row]  = sm_l[row] * fcr + tsum;
                sm_fc[row] = fcr;
            }
        }
        __syncthreads();

        {
            float f0 = sm_fc[r0], f1 = sm_fc[r1];
            #pragma unroll
            for (int nt = 0; nt < 8; nt++) {
                o[nt][0] *= f0; o[nt][1] *= f0;
                o[nt][2] *= f1; o[nt][3] *= f1;
            }
            #pragma unroll
            for (int ks = 0; ks < 4; ks++) {
                uint32_t ap[4], bv[8][2];
                int rowP = wid * 16 + (lane & 15);
                int koff = ks * 8 + ((lane >> 4) << 2);
                ldsm_x4(ap, smem_u32(Ps + rowP * 36 + koff));
                int nb = lane & 7;
                int koffb = ks * 8 + ((lane & 8) ? 4 : 0);
                #pragma unroll
                for (int nt = 0; nt < 8; nt++)
                    ldsm_x2(bv[nt], smem_u32(Vs + (nb + nt * 8) * 44 + koffb));
                #pragma unroll
                for (int nt = 0; nt < 8; nt++)
                    mma_tf32(o[nt], ap, bv[nt]);
            }
        }
    }

    __syncthreads();
    {
        float inv0 = 1.0f / sm_l[r0];
        float inv1 = 1.0f / sm_l[r1];
        #pragma unroll
        for (int nt = 0; nt < 8; nt++) {
            int col = nt * 8 + (lane & 3) * 2;
            float2 t0, t1;
            t0.x = rna(o[nt][0] * inv0); t0.y = rna(o[nt][1] * inv0);
            t1.x = rna(o[nt][2] * inv1); t1.y = rna(o[nt][3] * inv1);
            *(float2*)(O + base + (size_t)(q0 + r0) * DDIM + col) = t0;
            *(float2*)(O + base + (size_t)(q0 + r1) * DDIM + col) = t1;
        }
    }
}

// ---------------------------------------------------------------------------
// Launch sequence
// ---------------------------------------------------------------------------
extern "C" void kernel_launch(void* const* d_in, const int* in_sizes, int n_in,
                              void* d_out, int out_size) {
    const float* x     = (const float*)d_in[0];
    const float* ln1_g = (const float*)d_in[2];
    const float* ln1_b = (const float*)d_in[3];
    const float* W_q   = (const float*)d_in[4];
    const float* W_k   = (const float*)d_in[5];
    const float* W_v   = (const float*)d_in[6];
    const float* W_o   = (const float*)d_in[7];
    const float* ln2_g = (const float*)d_in[8];
    const float* ln2_b = (const float*)d_in[9];
    const float* fc1_W = (const float*)d_in[10];
    const float* fc1_b = (const float*)d_in[11];
    const float* fc2_W = (const float*)d_in[12];
    const float* fc2_b = (const float*)d_in[13];
    float* out = (float*)d_out;

    float *h, *qkv, *ctx, *x1, *f, *wqkv, *wo, *w1T, *w2T;
    cudaGetSymbolAddress((void**)&h,    g_h);
    cudaGetSymbolAddress((void**)&qkv,  g_qkv);
    cudaGetSymbolAddress((void**)&ctx,  g_ctx);
    cudaGetSymbolAddress((void**)&x1,   g_x1);
    cudaGetSymbolAddress((void**)&f,    g_f);
    cudaGetSymbolAddress((void**)&wqkv, g_wqkv);
    cudaGetSymbolAddress((void**)&wo,   g_wo);
    cudaGetSymbolAddress((void**)&w1T,  g_w1T);
    cudaGetSymbolAddress((void**)&w2T,  g_w2T);

    float* q = qkv;
    float* k = qkv + (size_t)MROWS * DDIM;
    float* v = qkv + (size_t)2 * MROWS * DDIM;

    cudaFuncSetAttribute(gemm_tc<false, false, false, true , true >, cudaFuncAttributeMaxDynamicSharedMemorySize, GEMM_SMEM);
    cudaFuncSetAttribute(gemm_tc<false, false, true , false, false>, cudaFuncAttributeMaxDynamicSharedMemorySize, GEMM_SMEM);
    cudaFuncSetAttribute(gemm_tc<true , true , false, true , false>, cudaFuncAttributeMaxDynamicSharedMemorySize, GEMM_SMEM);
    cudaFuncSetAttribute(gemm_tc<false, true , true , false, false>, cudaFuncAttributeMaxDynamicSharedMemorySize, GEMM_SMEM);
    cudaFuncSetAttribute(attn_kernel, cudaFuncAttributeMaxDynamicSharedMemorySize, ATTN_SMEM);

    int nDD = DDIM * DDIM / 4;

    round_kernel<<<(nDD + 255) / 256, 256>>>(W_q, wqkv,           nDD);
    round_kernel<<<(nDD + 255) / 256, 256>>>(W_k, wqkv + nDD * 4, nDD);
    round_kernel<<<(nDD + 255) / 256, 256>>>(W_v, wqkv + nDD * 8, nDD);
    ln_kernel<true><<<MROWS, 256>>>(x, ln1_g, ln1_b, h);
    // fused qkv = round(h @ Wqkv^T), split epilogue
    gemm_tc<false, false, false, true , true ><<<dim3(3 * DDIM / BNT, MROWS / BMT), GTHREADS, GEMM_SMEM>>>(
        h, wqkv, nullptr, nullptr, qkv, MROWS, 3 * DDIM, DDIM);
    // ctx = round(attention(q,k,v))   q-tile 128
    attn_kernel<<<dim3(LL / 128, BB * HH), 256, ATTN_SMEM>>>(q, k, v, ctx);
    round_kernel<<<(nDD + 255) / 256, 256>>>(W_o, wo, nDD);
    roundT_kernel<<<dim3(DFFN / 32, DDIM / 32), dim3(32, 8)>>>(fc1_W, w1T, DDIM, DFFN);
    roundT_kernel<<<dim3(DDIM / 32, DFFN / 32), dim3(32, 8)>>>(fc2_W, w2T, DFFN, DDIM);
    // x1 = x + ctx @ W_o^T
    gemm_tc<false, false, true , false, false><<<dim3(DDIM / BNT, MROWS / BMT), GTHREADS, GEMM_SMEM>>>(
        ctx, wo, nullptr, x, x1, MROWS, DDIM, DDIM);
    ln_kernel<true><<<MROWS, 256>>>(x1, ln2_g, ln2_b, h);
    // f = round(gelu(h @ w1T^T + b1))
    gemm_tc<true , true , false, true , false><<<dim3(DFFN / BNT, MROWS / BMT), GTHREADS, GEMM_SMEM>>>(
        h, w1T, fc1_b, nullptr, f, MROWS, DFFN, DDIM);
    // out = x1 + f @ w2T^T + b2
    gemm_tc<false, true , true , false, false><<<dim3(DDIM / BNT, MROWS / BMT), GTHREADS, GEMM_SMEM>>>(
        f, w2T, fc2_b, x1, out, MROWS, DDIM, DFFN);
}

// round 15
// speedup vs baseline: 1.1476x; 1.0320x over previous
#include <cuda_runtime.h>
#include <math.h>
#include <stdint.h>

// Problem dims (fixed)
#define BB   2
#define LL   2048
#define DDIM 1024
#define HH   16
#define DHD  64
#define DFFN 4096
#define MROWS (BB*LL)   // 4096 token rows

// ---------------------------------------------------------------------------
// Scratch (device globals; no runtime allocation allowed)
// ---------------------------------------------------------------------------
__device__ float g_h   [(size_t)MROWS * DDIM];
__device__ float g_qkv [(size_t)MROWS * DDIM * 3];   // q | k | v
__device__ float g_ctx [(size_t)MROWS * DDIM];
__device__ float g_x1  [(size_t)MROWS * DDIM];
__device__ float g_f   [(size_t)MROWS * DFFN];
// tf32-rounded weights (all NT: [N][K])
__device__ float g_wqkv[(size_t)3 * DDIM * DDIM];
__device__ float g_wo  [(size_t)DDIM * DDIM];
__device__ float g_w1T [(size_t)DFFN * DDIM];
__device__ float g_w2T [(size_t)DDIM * DFFN];

// ---------------------------------------------------------------------------
// PTX helpers
// ---------------------------------------------------------------------------
__device__ __forceinline__ uint32_t smem_u32(const void* p) {
    return (uint32_t)__cvta_generic_to_shared(p);
}
__device__ __forceinline__ void cp_async16(uint32_t dst, const void* src) {
    asm volatile("cp.async.cg.shared.global [%0], [%1], 16;" :: "r"(dst), "l"(src));
}
__device__ __forceinline__ void cp_commit() {
    asm volatile("cp.async.commit_group;");
}
template<int N>
__device__ __forceinline__ void cp_wait() {
    asm volatile("cp.async.wait_group %0;" :: "n"(N));
}
__device__ __forceinline__ float rna(float f) {
    uint32_t r;
    asm("cvt.rna.tf32.f32 %0, %1;" : "=r"(r) : "f"(f));
    return __uint_as_float(r);
}
__device__ __forceinline__ void mma_tf32(float* c, const uint32_t* a, const uint32_t* b) {
    asm volatile(
        "mma.sync.aligned.m16n8k8.row.col.f32.tf32.tf32.f32 "
        "{%0,%1,%2,%3},{%4,%5,%6,%7},{%8,%9},{%0,%1,%2,%3};"
        : "+f"(c[0]), "+f"(c[1]), "+f"(c[2]), "+f"(c[3])
        : "r"(a[0]), "r"(a[1]), "r"(a[2]), "r"(a[3]), "r"(b[0]), "r"(b[1]));
}
__device__ __forceinline__ void ldsm_x4(uint32_t* r, uint32_t addr) {
    asm volatile("ldmatrix.sync.aligned.m8n8.x4.shared.b16 {%0,%1,%2,%3}, [%4];"
        : "=r"(r[0]), "=r"(r[1]), "=r"(r[2]), "=r"(r[3]) : "r"(addr));
}
__device__ __forceinline__ void ldsm_x2(uint32_t* r, uint32_t addr) {
    asm volatile("ldmatrix.sync.aligned.m8n8.x2.shared.b16 {%0,%1}, [%2];"
        : "=r"(r[0]), "=r"(r[1]) : "r"(addr));
}

// ---------------------------------------------------------------------------
// Round fp32 -> tf32 (rna) elementwise, float4 per thread
// ---------------------------------------------------------------------------
__global__ void __launch_bounds__(256) round_kernel(const float* __restrict__ in,
                                                    float* __restrict__ out, int n4) {
    int i = blockIdx.x * 256 + threadIdx.x;
    if (i < n4) {
        float4 v = ((const float4*)in)[i];
        v.x = rna(v.x); v.y = rna(v.y); v.z = rna(v.z); v.w = rna(v.w);
        ((float4*)out)[i] = v;
    }
}

// ---------------------------------------------------------------------------
// Transpose + round: in[R][C] -> out[C][R] (tf32). block (32,8)
// ---------------------------------------------------------------------------
__global__ void __launch_bounds__(256) roundT_kernel(const float* __restrict__ in,
                                                     float* __restrict__ out,
                                                     int R, int C) {
    __shared__ float t[32][33];
    int bx = blockIdx.x * 32, by = blockIdx.y * 32;
    int x = threadIdx.x, y = threadIdx.y;
    #pragma unroll
    for (int i = 0; i < 32; i += 8)
        t[y + i][x] = in[(size_t)(by + y + i) * C + bx + x];
    __syncthreads();
    #pragma unroll
    for (int i = 0; i < 32; i += 8)
        out[(size_t)(bx + y + i) * R + by + x] = rna(t[x][y + i]);
}

// ---------------------------------------------------------------------------
// LayerNorm (validated)
// ---------------------------------------------------------------------------
template<bool RND>
__global__ void __launch_bounds__(256) ln_kernel(const float* __restrict__ x,
                                                 const float* __restrict__ g,
                                                 const float* __restrict__ b,
                                                 float* __restrict__ out) {
    int row = blockIdx.x;
    int t = threadIdx.x;
    const float4* xr = (const float4*)(x + (size_t)row * DDIM);
    float4 v = xr[t];
    __shared__ float sred[8];

    float s = v.x + v.y + v.z + v.w;
    #pragma unroll
    for (int o = 16; o > 0; o >>= 1) s += __shfl_xor_sync(0xffffffffu, s, o);
    if ((t & 31) == 0) sred[t >> 5] = s;
    __syncthreads();
    float tot = 0.f;
    #pragma unroll
    for (int w = 0; w < 8; w++) tot += sred[w];
    float mu = tot * (1.0f / DDIM);

    float dx = v.x - mu, dy = v.y - mu, dz = v.z - mu, dw = v.w - mu;
    float s2 = dx*dx + dy*dy + dz*dz + dw*dw;
    #pragma unroll
    for (int o = 16; o > 0; o >>= 1) s2 += __shfl_xor_sync(0xffffffffu, s2, o);
    __syncthreads();
    if ((t & 31) == 0) sred[t >> 5] = s2;
    __syncthreads();
    float tv = 0.f;
    #pragma unroll
    for (int w = 0; w < 8; w++) tv += sred[w];
    float rstd = rsqrtf(tv * (1.0f / DDIM) + 1e-5f);

    float4 gg = ((const float4*)g)[t];
    float4 bb = ((const float4*)b)[t];
    float4 o4;
    o4.x = dx * rstd * gg.x + bb.x;
    o4.y = dy * rstd * gg.y + bb.y;
    o4.z = dz * rstd * gg.z + bb.z;
    o4.w = dw * rstd * gg.w + bb.w;
    if (RND) { o4.x = rna(o4.x); o4.y = rna(o4.y); o4.z = rna(o4.z); o4.w = rna(o4.w); }
    ((float4*)(out + (size_t)row * DDIM))[t] = o4;
}

// ---------------------------------------------------------------------------
// tf32 tensor-core GEMM (NT): C[M,N] = A[M,K] @ B[N,K]^T  (validated R14)
// CTA 128x128x32, 4 warps (2x2), warp tile 64x64 (fat tile, deep MMA chains).
// Stride-36 smem, 3-stage cp.async ring, one __syncthreads per k-tile.
// ---------------------------------------------------------------------------
#define BMT 128
#define BNT 128
#define BKT 32
#define KSTR 36
#define NSTG 3
#define STG_F (BMT * KSTR)               // 4608 floats per stage per matrix
#define GEMM_SMEM (NSTG * STG_F * 2 * 4) // 110592 bytes
#define GTHREADS 128

template<bool GELU, bool BIAS, bool RES, bool RND, bool SPLIT>
__global__ void __launch_bounds__(GTHREADS) gemm_tc(
    const float* __restrict__ A, const float* __restrict__ Bm,
    const float* __restrict__ bias, const float* __restrict__ res,
    float* __restrict__ C, int M, int N, int K)
{
    extern __shared__ float sm[];
    float* As = sm;
    float* Bs = sm + NSTG * STG_F;

    int tid  = threadIdx.x;
    int lane = tid & 31;
    int wid  = tid >> 5;       // 0..3
    int wm   = wid >> 1;       // 0..1 (64-row band)
    int wn   = wid & 1;        // 0..1 (64-col band)
    int m0 = blockIdx.y * BMT;
    int n0 = blockIdx.x * BNT;

    float acc[4][8][4];
    #pragma unroll
    for (int i = 0; i < 4; i++)
        #pragma unroll
        for (int j = 0; j < 8; j++)
            #pragma unroll
            for (int r = 0; r < 4; r++) acc[i][j][r] = 0.f;

    auto issue = [&](int st, int k0) {
        float* as = As + st * STG_F;
        float* bs = Bs + st * STG_F;
        #pragma unroll
        for (int i = 0; i < 8; i++) {
            int idx = tid + i * GTHREADS;
            int row = idx >> 3, c = idx & 7;
            cp_async16(smem_u32(as + row * KSTR + c * 4),
                       A + (size_t)(m0 + row) * K + k0 + c * 4);
        }
        #pragma unroll
        for (int i = 0; i < 8; i++) {
            int idx = tid + i * GTHREADS;
            int row = idx >> 3, c = idx & 7;
            cp_async16(smem_u32(bs + row * KSTR + c * 4),
                       Bm + (size_t)(n0 + row) * K + k0 + c * 4);
        }
        cp_commit();
    };

    int nk = K / BKT;
    issue(0, 0);
    issue(1, BKT);

    for (int kt = 0; kt < nk; kt++) {
        if (kt + 1 < nk) cp_wait<1>(); else cp_wait<0>();
        __syncthreads();

        if (kt + 2 < nk) issue((kt + 2) % NSTG, (kt + 2) * BKT);

        const float* as = As + (kt % NSTG) * STG_F;
        const float* bs = Bs + (kt % NSTG) * STG_F;
        #pragma unroll
        for (int ks = 0; ks < 4; ks++) {
            uint32_t af[4][4], bf[8][2];
            {
                int rowbase = wm * 64 + (lane & 15);
                int koff = ks * 8 + ((lane >> 4) << 2);
                #pragma unroll
                for (int mt = 0; mt < 4; mt++)
                    ldsm_x4(af[mt], smem_u32(as + (rowbase + mt * 16) * KSTR + koff));
            }
            {
                int nb = wn * 64 + (lane & 7);
                int koff = ks * 8 + ((lane & 8) ? 4 : 0);
                #pragma unroll
                for (int nt = 0; nt < 8; nt++)
                    ldsm_x2(bf[nt], smem_u32(bs + (nb + nt * 8) * KSTR + koff));
            }
            #pragma unroll
            for (int mt = 0; mt < 4; mt++)
                #pragma unroll
                for (int nt = 0; nt < 8; nt++)
                    mma_tf32(acc[mt][nt], af[mt], bf[nt]);
        }
    }

    // ---- epilogue ----
    float* Cb = C;
    int ldc = N, ncol0 = n0;
    if (SPLIT) {
        Cb = C + (size_t)(n0 >> 10) * ((size_t)MROWS * DDIM);
        ldc = DDIM;
        ncol0 = n0 & 1023;
    }
    #pragma unroll
    for (int mt = 0; mt < 4; mt++) {
        #pragma unroll
        for (int nt = 0; nt < 8; nt++) {
            int row = m0 + wm * 64 + mt * 16 + (lane >> 2);
            int nc  = wn * 64 + nt * 8 + (lane & 3) * 2;
            int col = ncol0 + nc;
            #pragma unroll
            for (int half = 0; half < 2; half++) {
                int r = row + half * 8;
                float v0 = acc[mt][nt][half * 2 + 0];
                float v1 = acc[mt][nt][half * 2 + 1];
                if (BIAS) { v0 += bias[n0 + nc]; v1 += bias[n0 + nc + 1]; }
                if (GELU) {
                    v0 = 0.5f * v0 * (1.0f + erff(v0 * 0.70710678118654752f));
                    v1 = 0.5f * v1 * (1.0f + erff(v1 * 0.70710678118654752f));
                }
                if (RES) {
                    const float2 rr = *(const float2*)(res + (size_t)r * ldc + col);
                    v0 += rr.x; v1 += rr.y;
                }
                if (RND) { v0 = rna(v0); v1 = rna(v1); }
                float2 o2; o2.x = v0; o2.y = v1;
                *(float2*)(Cb + (size_t)r * ldc + col) = o2;
            }
        }
    }
}

// ---------------------------------------------------------------------------
// Causal flash attention, tf32 mma.sync, q-tile 128, cp.async-pipelined K/V.
// K and V loaded UNtransposed via cp.async, double-buffered; tile kt+1 is
// prefetched while tile kt computes. V fragments read scalar from Vs[c][d]
// (stride 72: 72 mod 32 = 8 -> conflict-free, same mapping as validated NN GEMM).
// Ks stride 68 (17 granules, mod 8 = 1) -> ldsm conflict-free.
// ---------------------------------------------------------------------------
#define QS_OFF 0                 // 128*68 = 8704
#define KS_OFF 8704
#define AKSTG  2176              // 32*68
#define VS_OFF (8704 + 2*2176)   // 13056
#define AVSTG  2304              // 32*72
#define PS_OFF (13056 + 2*2304)  // 17664, 128*36 = 4608
#define SMM_OFF (17664 + 4608)   // 22272
#define SML_OFF 22400
#define SMF_OFF 22528
#define ATTN_SMEM (22656 * 4)    // 90624 bytes

__global__ void __launch_bounds__(256) attn_kernel(
    const float* __restrict__ Q, const float* __restrict__ K,
    const float* __restrict__ V, float* __restrict__ O) {
    extern __shared__ float smf[];
    float* Qs = smf + QS_OFF;    // [r][d] stride 68
    float* Ks = smf + KS_OFF;    // 2 x [c][d] stride 68
    float* Vs = smf + VS_OFF;    // 2 x [c][d] stride 72
    float* Ps = smf + PS_OFF;    // [r][c] stride 36
    float* sm_m  = smf + SMM_OFF;
    float* sm_l  = smf + SML_OFF;
    float* sm_fc = smf + SMF_OFF;

    int tid  = threadIdx.x;
    int lane = tid & 31;
    int wid  = tid >> 5;          // 0..7: row band
    int qt = blockIdx.x;
    int bh = blockIdx.y;
    size_t base = (size_t)(bh / HH) * LL * DDIM + (size_t)(bh % HH) * DHD;
    int q0 = qt * 128;

    // Load Q tile [128][64] (float4 coalesced)
    #pragma unroll
    for (int i = 0; i < 8; i++) {
        int e = tid + i * 256;
        int r = e >> 4, c4 = (e & 15) * 4;
        *(float4*)&Qs[r * 68 + c4] = *(const float4*)(Q + base + (size_t)(q0 + r) * DDIM + c4);
    }
    if (tid < 128) { sm_m[tid] = -3.0e38f; sm_l[tid] = 0.f; }

    float o[8][4];
    #pragma unroll
    for (int nt = 0; nt < 8; nt++)
        #pragma unroll
        for (int r = 0; r < 4; r++) o[nt][r] = 0.f;

    int r0 = wid * 16 + (lane >> 2);
    int r1 = r0 + 8;

    // K/V tile loader: 32 rows x 64 floats = 512 16B chunks per matrix, 2/thread
    auto issue_kv = [&](int buf, int k0) {
        #pragma unroll
        for (int i = 0; i < 2; i++) {
            int idx = tid + i * 256;
            int c = idx >> 4, ch = idx & 15;
            cp_async16(smem_u32(Ks + buf * AKSTG + c * 68 + ch * 4),
                       K + base + (size_t)(k0 + c) * DDIM + ch * 4);
            cp_async16(smem_u32(Vs + buf * AVSTG + c * 72 + ch * 4),
                       V + base + (size_t)(k0 + c) * DDIM + ch * 4);
        }
        cp_commit();
    };

    int nkt = (q0 + 128) / 32;
    issue_kv(0, 0);

    for (int kt = 0; kt < nkt; kt++) {
        cp_wait<0>();        // tile kt complete (in flight since previous iter)
        __syncthreads();     // all threads past PV(kt-1); tile kt visible
        if (kt + 1 < nkt) issue_kv((kt + 1) & 1, (kt + 1) * 32);

        const float* ks = Ks + (kt & 1) * AKSTG;
        const float* vs = Vs + (kt & 1) * AVSTG;
        int k0 = kt * 32;

        // ---- S = Q K^T : warp computes 16 rows x 32 cols (4 n8 tiles) ----
        float cs[4][4];
        #pragma unroll
        for (int nt = 0; nt < 4; nt++)
            #pragma unroll
            for (int r = 0; r < 4; r++) cs[nt][r] = 0.f;
        #pragma unroll
        for (int ksu = 0; ksu < 8; ksu++) {
            uint32_t aq[4], bk[4][2];
            int rowQ = wid * 16 + (lane & 15);
            int koff = ksu * 8 + ((lane >> 4) << 2);
            ldsm_x4(aq, smem_u32(Qs + rowQ * 68 + koff));
            int nb = lane & 7;
            int koffb = ksu * 8 + ((lane & 8) ? 4 : 0);
            #pragma unroll
            for (int nt = 0; nt < 4; nt++)
                ldsm_x2(bk[nt], smem_u32(ks + (nb + nt * 8) * 68 + koffb));
            #pragma unroll
            for (int nt = 0; nt < 4; nt++)
                mma_tf32(cs[nt], aq, bk[nt]);
        }
        // scale, mask, store S -> Ps
        {
            int cb = (lane & 3) * 2;
            #pragma unroll
            for (int nt = 0; nt < 4; nt++) {
                int c0 = cb + nt * 8;
                float s00 = cs[nt][0] * 0.125f, s01 = cs[nt][1] * 0.125f;
                float s10 = cs[nt][2] * 0.125f, s11 = cs[nt][3] * 0.125f;
                if (k0 + c0     > q0 + r0) s00 = -3.0e38f;
                if (k0 + c0 + 1 > q0 + r0) s01 = -3.0e38f;
                if (k0 + c0     > q0 + r1) s10 = -3.0e38f;
                if (k0 + c0 + 1 > q0 + r1) s11 = -3.0e38f;
                float2 t0; t0.x = s00; t0.y = s01;
                float2 t1; t1.x = s10; t1.y = s11;
                *(float2*)&Ps[r0 * 36 + c0] = t0;
                *(float2*)&Ps[r1 * 36 + c0] = t1;
            }
        }
        __syncthreads();

        // ---- online softmax: 2 threads/row, 16 cols each ----
        {
            int row = tid >> 1;
            int qd  = tid & 1;
            float sv[16];
            #pragma unroll
            for (int j = 0; j < 16; j++) sv[j] = Ps[row * 36 + qd * 16 + j];
            float tmax = sv[0];
            #pragma unroll
            for (int j = 1; j < 16; j++) tmax = fmaxf(tmax, sv[j]);
            tmax = fmaxf(tmax, __shfl_xor_sync(0xffffffffu, tmax, 1));
            float mold = sm_m[row];
            float newm = fmaxf(mold, tmax);
            float fcr  = __expf(mold - newm);
            float tsum = 0.f;
            #pragma unroll
            for (int j = 0; j < 16; j++) {
                float p = __expf(sv[j] - newm);
                tsum += p;
                sv[j] = rna(p);
            }
            #pragma unroll
            for (int j = 0; j < 16; j++) Ps[row * 36 + qd * 16 + j] = sv[j];
            tsum += __shfl_xor_sync(0xffffffffu, tsum, 1);
            if (qd == 0) {
                sm_m[row]  = newm;
                sm_l[row]  = sm_l[row] * fcr + tsum;
                sm_fc[row] = fcr;
            }
        }
        __syncthreads();

        // ---- O = O*fc + P V : warp 16 rows x 64 cols; V fragments scalar ----
        {
            float f0 = sm_fc[r0], f1 = sm_fc[r1];
            #pragma unroll
            for (int nt = 0; nt < 8; nt++) {
                o[nt][0] *= f0; o[nt][1] *= f0;
                o[nt][2] *= f1; o[nt][3] *= f1;
            }
            #pragma unroll
            for (int ksu = 0; ksu < 4; ksu++) {
                uint32_t ap[4], bv[8][2];
                int rowP = wid * 16 + (lane & 15);
                int koff = ksu * 8 + ((lane >> 4) << 2);
                ldsm_x4(ap, smem_u32(Ps + rowP * 36 + koff));
                int ak = ksu * 8 + (lane & 3);
                int bn = lane >> 2;
                #pragma unroll
                for (int nt = 0; nt < 8; nt++) {
                    bv[nt][0] = __float_as_uint(vs[(ak    ) * 72 + nt * 8 + bn]);
                    bv[nt][1] = __float_as_uint(vs[(ak + 4) * 72 + nt * 8 + bn]);
                }
                #pragma unroll
                for (int nt = 0; nt < 8; nt++)
                    mma_tf32(o[nt], ap, bv[nt]);
            }
        }
    }

    __syncthreads();
    // epilogue
    {
        float inv0 = 1.0f / sm_l[r0];
        float inv1 = 1.0f / sm_l[r1];
        #pragma unroll
        for (int nt = 0; nt < 8; nt++) {
            int col = nt * 8 + (lane & 3) * 2;
            float2 t0, t1;
            t0.x = rna(o[nt][0] * inv0); t0.y = rna(o[nt][1] * inv0);
            t1.x = rna(o[nt][2] * inv1); t1.y = rna(o[nt][3] * inv1);
            *(float2*)(O + base + (size_t)(q0 + r0) * DDIM + col) = t0;
            *(float2*)(O + base + (size_t)(q0 + r1) * DDIM + col) = t1;
        }
    }
}

// ---------------------------------------------------------------------------
// Launch sequence
// ---------------------------------------------------------------------------
extern "C" void kernel_launch(void* const* d_in, const int* in_sizes, int n_in,
                              void* d_out, int out_size) {
    const float* x     = (const float*)d_in[0];
    const float* ln1_g = (const float*)d_in[2];
    const float* ln1_b = (const float*)d_in[3];
    const float* W_q   = (const float*)d_in[4];
    const float* W_k   = (const float*)d_in[5];
    const float* W_v   = (const float*)d_in[6];
    const float* W_o   = (const float*)d_in[7];
    const float* ln2_g = (const float*)d_in[8];
    const float* ln2_b = (const float*)d_in[9];
    const float* fc1_W = (const float*)d_in[10];
    const float* fc1_b = (const float*)d_in[11];
    const float* fc2_W = (const float*)d_in[12];
    const float* fc2_b = (const float*)d_in[13];
    float* out = (float*)d_out;

    float *h, *qkv, *ctx, *x1, *f, *wqkv, *wo, *w1T, *w2T;
    cudaGetSymbolAddress((void**)&h,    g_h);
    cudaGetSymbolAddress((void**)&qkv,  g_qkv);
    cudaGetSymbolAddress((void**)&ctx,  g_ctx);
    cudaGetSymbolAddress((void**)&x1,   g_x1);
    cudaGetSymbolAddress((void**)&f,    g_f);
    cudaGetSymbolAddress((void**)&wqkv, g_wqkv);
    cudaGetSymbolAddress((void**)&wo,   g_wo);
    cudaGetSymbolAddress((void**)&w1T,  g_w1T);
    cudaGetSymbolAddress((void**)&w2T,  g_w2T);

    float* q = qkv;
    float* k = qkv + (size_t)MROWS * DDIM;
    float* v = qkv + (size_t)2 * MROWS * DDIM;

    cudaFuncSetAttribute(gemm_tc<false, false, false, true , true >, cudaFuncAttributeMaxDynamicSharedMemorySize, GEMM_SMEM);
    cudaFuncSetAttribute(gemm_tc<false, false, true , false, false>, cudaFuncAttributeMaxDynamicSharedMemorySize, GEMM_SMEM);
    cudaFuncSetAttribute(gemm_tc<true , true , false, true , false>, cudaFuncAttributeMaxDynamicSharedMemorySize, GEMM_SMEM);
    cudaFuncSetAttribute(gemm_tc<false, true , true , false, false>, cudaFuncAttributeMaxDynamicSharedMemorySize, GEMM_SMEM);
    cudaFuncSetAttribute(attn_kernel, cudaFuncAttributeMaxDynamicSharedMemorySize, ATTN_SMEM);

    int nDD = DDIM * DDIM / 4;

    round_kernel<<<(nDD + 255) / 256, 256>>>(W_q, wqkv,           nDD);
    round_kernel<<<(nDD + 255) / 256, 256>>>(W_k, wqkv + nDD * 4, nDD);
    round_kernel<<<(nDD + 255) / 256, 256>>>(W_v, wqkv + nDD * 8, nDD);
    ln_kernel<true><<<MROWS, 256>>>(x, ln1_g, ln1_b, h);
    // fused qkv = round(h @ Wqkv^T), split epilogue
    gemm_tc<false, false, false, true , true ><<<dim3(3 * DDIM / BNT, MROWS / BMT), GTHREADS, GEMM_SMEM>>>(
        h, wqkv, nullptr, nullptr, qkv, MROWS, 3 * DDIM, DDIM);
    // ctx = round(attention(q,k,v))   q-tile 128, cp.async K/V pipeline
    attn_kernel<<<dim3(LL / 128, BB * HH), 256, ATTN_SMEM>>>(q, k, v, ctx);
    round_kernel<<<(nDD + 255) / 256, 256>>>(W_o, wo, nDD);
    roundT_kernel<<<dim3(DFFN / 32, DDIM / 32), dim3(32, 8)>>>(fc1_W, w1T, DDIM, DFFN);
    roundT_kernel<<<dim3(DDIM / 32, DFFN / 32), dim3(32, 8)>>>(fc2_W, w2T, DFFN, DDIM);
    // x1 = x + ctx @ W_o^T
    gemm_tc<false, false, true , false, false><<<dim3(DDIM / BNT, MROWS / BMT), GTHREADS, GEMM_SMEM>>>(
        ctx, wo, nullptr, x, x1, MROWS, DDIM, DDIM);
    ln_kernel<true><<<MROWS, 256>>>(x1, ln2_g, ln2_b, h);
    // f = round(gelu(h @ w1T^T + b1))
    gemm_tc<true , true , false, true , false><<<dim3(DFFN / BNT, MROWS / BMT), GTHREADS, GEMM_SMEM>>>(
        h, w1T, fc1_b, nullptr, f, MROWS, DFFN, DDIM);
    // out = x1 + f @ w2T^T + b2
    gemm_tc<false, true , true , false, false><<<dim3(DDIM / BNT, MROWS / BMT), GTHREADS, GEMM_SMEM>>>(
        f, w2T, fc2_b, x1, out, MROWS, DDIM, DFFN);
}